// round 9
// baseline (speedup 1.0000x reference)
#include <cuda_runtime.h>
#include <cuda_bf16.h>
#include <cstdint>

// ---------------------------------------------------------------------------
// GraphSAGE: 2x (SAGEConv -> BN(train) -> ReLU) -> Linear[128->2]
//  - CSR build on device (hist -> multi-block scan -> fill)
//  - warp-per-node gather-mean (fp32); layer-1 applies BN+ReLU inline per edge
//  - GEMM  [agg | in] @ [Wl;Wr] + b  via mma.sync m16n8k16 bf16 (split x3),
//    fp32->bf16 hi/lo split done inline in the A-tile loader,
//    BN column stats fused into the GEMM epilogue (atomicAdd)
//  - BN finalize (self-zeroing stats); final BN+ReLU+[128,2] linear -> d_out
// ---------------------------------------------------------------------------

#define MAXN 50000
#define MAXE 1048576

__device__ float g_hpre[MAXN * 128];
__device__ float g_agg [MAXN * 128];
__device__ __nv_bfloat16 g_wth [2][128 * 256];   // [layer][n][k] transposed hi
__device__ __nv_bfloat16 g_wtl [2][128 * 256];   // lo
__device__ int   g_deg   [MAXN];
__device__ int   g_rowptr[MAXN + 1];
__device__ int   g_cursor[MAXN];
__device__ int   g_src   [MAXE];
__device__ int   g_dst   [MAXE];
__device__ int   g_ssort [MAXE];
__device__ int   g_bsum  [64];
__device__ int   g_boff  [64];
__device__ float g_stats [256];
__device__ float g_scale [128];
__device__ float g_shift [128];
__device__ int   g_is64;

// ---------------- PTX helpers ----------------
__device__ __forceinline__ uint32_t s2u(const void* p) {
    uint32_t a;
    asm("{ .reg .u64 t; cvta.to.shared.u64 t, %1; cvt.u32.u64 %0, t; }"
        : "=r"(a) : "l"(p));
    return a;
}

__device__ __forceinline__ void ldm4(uint32_t* r, uint32_t addr) {
    asm volatile("ldmatrix.sync.aligned.m8n8.x4.shared.b16 {%0,%1,%2,%3}, [%4];"
        : "=r"(r[0]), "=r"(r[1]), "=r"(r[2]), "=r"(r[3]) : "r"(addr));
}

__device__ __forceinline__ void mma16816(float* d, const uint32_t* a,
                                         uint32_t b0, uint32_t b1) {
    asm volatile(
        "mma.sync.aligned.m16n8k16.row.col.f32.bf16.bf16.f32 "
        "{%0,%1,%2,%3}, {%4,%5,%6,%7}, {%8,%9}, {%0,%1,%2,%3};"
        : "+f"(d[0]), "+f"(d[1]), "+f"(d[2]), "+f"(d[3])
        : "r"(a[0]), "r"(a[1]), "r"(a[2]), "r"(a[3]), "r"(b0), "r"(b1));
}

__device__ __forceinline__ uint32_t pkbf(float a, float b) {
    __nv_bfloat162 h = __halves2bfloat162(__float2bfloat16(a), __float2bfloat16(b));
    return *(uint32_t*)&h;
}

// smem layout for GEMM (bytes)
#define SM_A  0            // A: 2 halves x 4 k-sections x [128r][64c bf16] = 131072
#define SM_W  131072       // W chunk: 2 halves x 2 k-sections x [128n][64k] = 65536
#define SM_TOTAL 196608

// ---------------- edge preprocessing ----------------
__global__ void k_detect(const void* __restrict__ ei, int E) {
    if (threadIdx.x == 0) {
        const int* p = (const int*)ei;
        int m = E < 64 ? E : 64, is64 = 1;
        for (int i = 0; i < m; i++)
            if (p[2 * i + 1] != 0) { is64 = 0; break; }
        g_is64 = is64;
    }
}

__global__ void k_zero_build(int n) {
    int i = blockIdx.x * blockDim.x + threadIdx.x;
    if (i < n) { g_deg[i] = 0; g_cursor[i] = 0; }
    if (i < 256) g_stats[i] = 0.f;
}

__global__ void k_edges(const void* __restrict__ ei, int E) {
    int i = blockIdx.x * blockDim.x + threadIdx.x;
    if (i >= E) return;
    int s, d;
    if (g_is64) {
        const long long* q = (const long long*)ei;
        s = (int)q[i]; d = (int)q[E + i];
    } else {
        const int* q = (const int*)ei;
        s = q[i]; d = q[E + i];
    }
    g_src[i] = s; g_dst[i] = d;
    atomicAdd(&g_deg[d], 1);
}

// ---------------- multi-block scan: deg -> rowptr ----------------
__global__ void k_scan1(int n) {
    __shared__ int warpsums[8];
    int tid = threadIdx.x, lane = tid & 31, wid = tid >> 5;
    int i0 = blockIdx.x * 2048 + tid * 8;
    int v[8], tot = 0;
    #pragma unroll
    for (int j = 0; j < 8; j++) {
        v[j] = (i0 + j < n) ? g_deg[i0 + j] : 0;
        tot += v[j];
    }
    int x = tot;
    #pragma unroll
    for (int off = 1; off < 32; off <<= 1) {
        int t = __shfl_up_sync(0xffffffffu, x, off);
        if (lane >= off) x += t;
    }
    if (lane == 31) warpsums[wid] = x;
    __syncthreads();
    if (wid == 0) {
        int w = (lane < 8) ? warpsums[lane] : 0;
        #pragma unroll
        for (int off = 1; off < 8; off <<= 1) {
            int t = __shfl_up_sync(0xffffffffu, w, off);
            if (lane >= off) w += t;
        }
        if (lane < 8) warpsums[lane] = w;
    }
    __syncthreads();
    int wpref = (wid > 0) ? warpsums[wid - 1] : 0;
    int run = wpref + (x - tot);
    #pragma unroll
    for (int j = 0; j < 8; j++) {
        run += v[j];
        if (i0 + j < n) g_rowptr[i0 + j + 1] = run;
    }
    if (tid == 0) g_bsum[blockIdx.x] = warpsums[7];
}

__global__ void k_scan2(int nb) {
    int lane = threadIdx.x;
    int a = (2 * lane     < nb) ? g_bsum[2 * lane]     : 0;
    int b = (2 * lane + 1 < nb) ? g_bsum[2 * lane + 1] : 0;
    int t = a + b;
    int x = t;
    #pragma unroll
    for (int off = 1; off < 32; off <<= 1) {
        int u = __shfl_up_sync(0xffffffffu, x, off);
        if (lane >= off) x += u;
    }
    int excl = x - t;
    if (2 * lane     < nb) g_boff[2 * lane]     = excl;
    if (2 * lane + 1 < nb) g_boff[2 * lane + 1] = excl + a;
}

__global__ void k_scan3(int n) {
    int i = blockIdx.x * blockDim.x + threadIdx.x;
    if (i == 0) g_rowptr[0] = 0;
    if (i < n) g_rowptr[i + 1] += g_boff[i >> 11];
}

__global__ void k_fill(int E) {
    int i = blockIdx.x * blockDim.x + threadIdx.x;
    if (i >= E) return;
    int d = g_dst[i];
    int p = g_rowptr[d] + atomicAdd(&g_cursor[d], 1);
    g_ssort[p] = g_src[i];
}

__global__ void k_prep_w(const float* __restrict__ Wl,
                         const float* __restrict__ Wr, int layer) {
    int i = blockIdx.x * blockDim.x + threadIdx.x;   // 128*256
    if (i >= 128 * 256) return;
    int nn = i >> 8, k = i & 255;
    float v = (k < 128) ? __ldg(&Wl[k * 128 + nn]) : __ldg(&Wr[(k - 128) * 128 + nn]);
    __nv_bfloat16 h = __float2bfloat16(v);
    g_wth[layer][i] = h;
    g_wtl[layer][i] = __float2bfloat16(v - __bfloat162float(h));
}

// ---------------- aggregation: warp per node, mean -> g_agg fp32 ----------------
// layer==1: input is g_hpre with BN(scale,shift)+ReLU applied per gathered row.
__global__ void k_aggregate(const float* __restrict__ xext, int layer, int n) {
    int gw   = (blockIdx.x * blockDim.x + threadIdx.x) >> 5;
    int lane = threadIdx.x & 31;
    if (gw >= n) return;
    const float4* in4 = (const float4*)(layer ? g_hpre : xext);
    float4 sc, sh;
    if (layer) {
        sc = ((const float4*)g_scale)[lane];
        sh = ((const float4*)g_shift)[lane];
    }
    int e0 = g_rowptr[gw], e1 = g_rowptr[gw + 1];
    float4 acc = make_float4(0.f, 0.f, 0.f, 0.f);
    for (int e = e0; e < e1; e++) {
        int s = __ldg(&g_ssort[e]);
        float4 v = __ldg(&in4[s * 32 + lane]);
        if (layer) {
            v.x = fmaxf(v.x * sc.x + sh.x, 0.f);
            v.y = fmaxf(v.y * sc.y + sh.y, 0.f);
            v.z = fmaxf(v.z * sc.z + sh.z, 0.f);
            v.w = fmaxf(v.w * sc.w + sh.w, 0.f);
        }
        acc.x += v.x; acc.y += v.y; acc.z += v.z; acc.w += v.w;
    }
    float inv = 1.0f / fmaxf((float)(e1 - e0), 1.0f);
    acc.x *= inv; acc.y *= inv; acc.z *= inv; acc.w *= inv;
    ((float4*)g_agg)[gw * 32 + lane] = acc;
}

// ---------------- mma.sync GEMM + fused BN column stats ----------------
// Block tile: 128 rows x 128 cols, K=256 in 2 W-chunks of 128.
// A loaded as fp32 ([agg | self]) and split to bf16 hi/lo inline; for layer 1
// the self path applies BN+ReLU first. Products hi*hi + hi*lo + lo*hi.
// Epilogue: add bias, store fp32, atomicAdd column sum/sumsq to g_stats.
__global__ void __launch_bounds__(256, 1)
k_gemm_mma(int layer, int use_x, const float* __restrict__ xext,
           const float* __restrict__ bias, int n) {
    extern __shared__ char smem[];
    uint32_t sb = s2u(smem);
    int tid  = threadIdx.x;
    int wid  = tid >> 5;
    int lane = tid & 31;
    int row0 = blockIdx.x * 128;

    // ---- load A tile fp32, split to hi/lo bf16 in smem: 8192 float4 ----
    const float4* agg4 = (const float4*)g_agg;
    for (int i = tid; i < 8192; i += 256) {
        int r  = i >> 6;                 // 0..127
        int c4 = i & 63;                 // float4 index over 256 cols
        int c0 = c4 * 4;
        int row = row0 + r;
        float4 v = make_float4(0.f, 0.f, 0.f, 0.f);
        if (row < n) {
            if (c0 < 128) {
                v = __ldg(&agg4[row * 32 + c4]);
            } else if (use_x) {
                v = __ldg(&((const float4*)xext)[row * 32 + (c4 - 32)]);
            } else {
                int cc = c0 - 128;
                v = *(const float4*)(g_hpre + (size_t)row * 128 + cc);
                float4 sc = *(const float4*)(g_scale + cc);
                float4 sh = *(const float4*)(g_shift + cc);
                v.x = fmaxf(v.x * sc.x + sh.x, 0.f);
                v.y = fmaxf(v.y * sc.y + sh.y, 0.f);
                v.z = fmaxf(v.z * sc.z + sh.z, 0.f);
                v.w = fmaxf(v.w * sc.w + sh.w, 0.f);
            }
        }
        // split
        float hx = __bfloat162float(__float2bfloat16(v.x));
        float hy = __bfloat162float(__float2bfloat16(v.y));
        float hz = __bfloat162float(__float2bfloat16(v.z));
        float hw = __bfloat162float(__float2bfloat16(v.w));
        uint2 hi = make_uint2(pkbf(v.x, v.y), pkbf(v.z, v.w));
        uint2 lo = make_uint2(pkbf(v.x - hx, v.y - hy), pkbf(v.z - hz, v.w - hw));
        int s   = c0 >> 6;
        int cc  = c0 & 63;
        int gin = cc >> 3;               // 16B granule
        int hg  = (cc >> 2) & 1;         // which 8B half
        char* dst = smem + SM_A + s * 16384 + r * 128 +
                    ((gin ^ (r & 7)) * 16) + hg * 8;
        *(uint2*)dst = hi;
        *(uint2*)(dst + 65536) = lo;
    }

    int wm = wid >> 1, wn = wid & 1;
    int m0 = wm * 32, n0 = wn * 64;
    float acc[2][8][4];
    #pragma unroll
    for (int mf = 0; mf < 2; mf++)
        #pragma unroll
        for (int nf = 0; nf < 8; nf++)
            #pragma unroll
            for (int q = 0; q < 4; q++) acc[mf][nf][q] = 0.f;

    int lx    = lane & 7;
    int aRow  = lane & 15;
    int aKoff = lane >> 4;
    int wRow  = (lane & 7) + ((lane >> 4) << 3);
    int wKoff = (lane >> 3) & 1;

    const __nv_bfloat16* wth = g_wth[layer];
    const __nv_bfloat16* wtl = g_wtl[layer];

    #pragma unroll 1
    for (int kc = 0; kc < 2; kc++) {
        __syncthreads();
        // ---- load W chunk (hi + lo), 4096 uint4 ----
        for (int i = tid; i < 4096; i += 256) {
            int half = i >> 11;
            int j = i & 2047;
            int r  = j >> 4;
            int kin = (j & 15) * 8;
            int s2 = kin >> 6;
            int gin = (kin >> 3) & 7;
            const __nv_bfloat16* base = half ? wtl : wth;
            uint4 v = __ldg((const uint4*)(base + (size_t)r * 256 + kc * 128 + kin));
            *(uint4*)(smem + SM_W + half * 32768 + s2 * 16384 + r * 128 +
                      ((gin ^ (r & 7)) * 16)) = v;
        }
        __syncthreads();

        #pragma unroll 1
        for (int ksl = 0; ksl < 8; ksl++) {
            int ks   = kc * 8 + ksl;
            int sA   = ks >> 2;
            int kgA  = (ks & 3) * 2 + aKoff;
            int s2   = ksl >> 2;
            int kgW  = (ksl & 3) * 2 + wKoff;

            #pragma unroll
            for (int ah = 0; ah < 2; ah++) {
                uint32_t af[2][4];
                #pragma unroll
                for (int mf = 0; mf < 2; mf++) {
                    int r = m0 + mf * 16 + aRow;
                    uint32_t addr = sb + SM_A + ah * 65536 + sA * 16384 +
                                    r * 128 + ((kgA ^ lx) * 16);
                    ldm4(af[mf], addr);
                }
                int nwh = (ah == 0) ? 2 : 1;        // Ah*{Wh,Wl}, Al*Wh
                #pragma unroll
                for (int wh = 0; wh < 2; wh++) {
                    if (wh >= nwh) break;
                    #pragma unroll
                    for (int np = 0; np < 4; np++) {
                        uint32_t wf[4];
                        int r = n0 + np * 16 + wRow;
                        uint32_t addr = sb + SM_W + wh * 32768 + s2 * 16384 +
                                        r * 128 + ((kgW ^ lx) * 16);
                        ldm4(wf, addr);
                        #pragma unroll
                        for (int mf = 0; mf < 2; mf++) {
                            mma16816(acc[mf][np * 2],     af[mf], wf[0], wf[1]);
                            mma16816(acc[mf][np * 2 + 1], af[mf], wf[2], wf[3]);
                        }
                    }
                }
            }
        }
    }

    // ---- epilogue: add bias, store fp32, fused BN column stats ----
    #pragma unroll
    for (int nf = 0; nf < 8; nf++) {
        int col = n0 + nf * 8 + (lane & 3) * 2;
        float bx = __ldg(&bias[col]), by = __ldg(&bias[col + 1]);
        float s0 = 0.f, q0 = 0.f, s1 = 0.f, q1 = 0.f;
        #pragma unroll
        for (int mf = 0; mf < 2; mf++) {
            int row = row0 + m0 + mf * 16 + (lane >> 2);
            if (row < n) {
                float a = acc[mf][nf][0] + bx, b = acc[mf][nf][1] + by;
                *(float2*)(g_hpre + (size_t)row * 128 + col) = make_float2(a, b);
                s0 += a; q0 += a * a; s1 += b; q1 += b * b;
            }
            if (row + 8 < n) {
                float a = acc[mf][nf][2] + bx, b = acc[mf][nf][3] + by;
                *(float2*)(g_hpre + (size_t)(row + 8) * 128 + col) = make_float2(a, b);
                s0 += a; q0 += a * a; s1 += b; q1 += b * b;
            }
        }
        #pragma unroll
        for (int off = 4; off < 32; off <<= 1) {
            s0 += __shfl_xor_sync(0xffffffffu, s0, off);
            q0 += __shfl_xor_sync(0xffffffffu, q0, off);
            s1 += __shfl_xor_sync(0xffffffffu, s1, off);
            q1 += __shfl_xor_sync(0xffffffffu, q1, off);
        }
        if (lane < 4) {
            int c = n0 + nf * 8 + lane * 2;
            atomicAdd(&g_stats[c],       s0);
            atomicAdd(&g_stats[128 + c], q0);
            atomicAdd(&g_stats[c + 1],       s1);
            atomicAdd(&g_stats[128 + c + 1], q1);
        }
    }
}

// ---------------- BatchNorm finalize (self-zeroing stats) ----------------
__global__ void k_finalize(const float* __restrict__ gamma,
                           const float* __restrict__ beta, int n) {
    int t = threadIdx.x;
    float invn = 1.0f / (float)n;
    float mu  = g_stats[t] * invn;
    float var = fmaxf(g_stats[128 + t] * invn - mu * mu, 0.f);
    g_stats[t] = 0.f;
    g_stats[128 + t] = 0.f;
    float rs = rsqrtf(var + 1e-5f);
    float sc = __ldg(&gamma[t]) * rs;
    g_scale[t] = sc;
    g_shift[t] = __ldg(&beta[t]) - mu * sc;
}

// BN apply + ReLU + [128,2] linear -> d_out
__global__ void k_apply_out(const float* __restrict__ Wout,
                            const float* __restrict__ bout,
                            float* __restrict__ out, int n) {
    int gw   = (blockIdx.x * blockDim.x + threadIdx.x) >> 5;
    int lane = threadIdx.x & 31;
    if (gw >= n) return;
    float4 v  = ((const float4*)g_hpre)[gw * 32 + lane];
    float4 sc = ((const float4*)g_scale)[lane];
    float4 sh = ((const float4*)g_shift)[lane];
    v.x = fmaxf(v.x * sc.x + sh.x, 0.f);
    v.y = fmaxf(v.y * sc.y + sh.y, 0.f);
    v.z = fmaxf(v.z * sc.z + sh.z, 0.f);
    v.w = fmaxf(v.w * sc.w + sh.w, 0.f);
    const float4* W4 = (const float4*)Wout;
    float4 wa = __ldg(&W4[lane * 2]);
    float4 wb = __ldg(&W4[lane * 2 + 1]);
    float s0 = v.x * wa.x + v.y * wa.z + v.z * wb.x + v.w * wb.z;
    float s1 = v.x * wa.y + v.y * wa.w + v.z * wb.y + v.w * wb.w;
    #pragma unroll
    for (int off = 16; off; off >>= 1) {
        s0 += __shfl_xor_sync(0xffffffffu, s0, off);
        s1 += __shfl_xor_sync(0xffffffffu, s1, off);
    }
    if (lane == 0) {
        out[gw * 2 + 0] = s0 + __ldg(&bout[0]);
        out[gw * 2 + 1] = s1 + __ldg(&bout[1]);
    }
}

// ---------------------------------------------------------------------------
extern "C" void kernel_launch(void* const* d_in, const int* in_sizes, int n_in,
                              void* d_out, int out_size) {
    const float* x    = (const float*)d_in[0];
    const void*  ei   = d_in[1];
    const float* Wl0  = (const float*)d_in[2];
    const float* Wr0  = (const float*)d_in[3];
    const float* b0   = (const float*)d_in[4];
    const float* gm0  = (const float*)d_in[5];
    const float* be0  = (const float*)d_in[6];
    const float* Wl1  = (const float*)d_in[7];
    const float* Wr1  = (const float*)d_in[8];
    const float* b1   = (const float*)d_in[9];
    const float* gm1  = (const float*)d_in[10];
    const float* be1  = (const float*)d_in[11];
    const float* Wout = (const float*)d_in[12];
    const float* bout = (const float*)d_in[13];
    float* out = (float*)d_out;

    int E = in_sizes[1] / 2;  if (E > MAXE) E = MAXE;
    int n = out_size / 2;     if (n > MAXN) n = MAXN;

    cudaFuncSetAttribute(k_gemm_mma,
        cudaFuncAttributeMaxDynamicSharedMemorySize, SM_TOTAL);

    int eb = (E + 255) / 256;
    int nb = (n + 255) / 256;
    int ab = (n * 32 + 255) / 256;          // warp-per-node launches
    int gb = (n + 127) / 128;
    int sb = (n + 2047) / 2048;             // scan blocks

    // --- CSR build + weight prep ---
    k_detect    <<<1, 32>>>(ei, E);
    k_zero_build<<<nb, 256>>>(n);
    k_edges     <<<eb, 256>>>(ei, E);
    k_scan1     <<<sb, 256>>>(n);
    k_scan2     <<<1, 32>>>(sb);
    k_scan3     <<<nb, 256>>>(n);
    k_fill      <<<eb, 256>>>(E);
    k_prep_w    <<<128, 256>>>(Wl0, Wr0, 0);
    k_prep_w    <<<128, 256>>>(Wl1, Wr1, 1);

    // --- layer 0 ---
    k_aggregate <<<ab, 256>>>(x, 0, n);
    k_gemm_mma  <<<gb, 256, SM_TOTAL>>>(0, 1, x, b0, n);
    k_finalize  <<<1, 128>>>(gm0, be0, n);

    // --- layer 1 (BN+ReLU of layer 0 applied inline in consumers) ---
    k_aggregate <<<ab, 256>>>(nullptr, 1, n);
    k_gemm_mma  <<<gb, 256, SM_TOTAL>>>(1, 0, nullptr, b1, n);
    k_finalize  <<<1, 128>>>(gm1, be1, n);

    // --- fused BN+ReLU+Linear[128->2] -> d_out ---
    k_apply_out <<<ab, 256>>>(Wout, bout, out, n);
}

// round 10
// speedup vs baseline: 1.0636x; 1.0636x over previous
#include <cuda_runtime.h>
#include <cuda_bf16.h>
#include <cuda_fp16.h>
#include <cstdint>

// ---------------------------------------------------------------------------
// GraphSAGE: 2x (SAGEConv -> BN(train) -> ReLU) -> Linear[128->2]
//  - CSR build on device (hist -> multi-block scan -> fill)
//  - gather-mean over fp16 activations (halved L2 traffic), fp32 accumulate
//  - GEMM  [agg | in] @ [Wl;Wr] + b  via mma.sync m16n8k16 bf16 (split x3),
//    fp32->bf16 hi/lo split inline in the A-tile loader,
//    BN column stats fused into the GEMM epilogue (atomicAdd)
//  - BN finalize (self-zeroing); final BN+ReLU+[128,2] linear -> d_out
// ---------------------------------------------------------------------------

#define MAXN 50000
#define MAXE 1048576

__device__ float g_hpre[MAXN * 128];
__device__ float g_agg [MAXN * 128];
__device__ __half g_xhalf[MAXN * 128];   // fp16 copy of x (gather source, L0)
__device__ __half g_hhalf[MAXN * 128];   // fp16 relu(bn(hpre)) (gather source, L1)
__device__ __nv_bfloat16 g_wth [2][128 * 256];   // [layer][n][k] transposed hi
__device__ __nv_bfloat16 g_wtl [2][128 * 256];   // lo
__device__ int   g_deg   [MAXN];
__device__ int   g_rowptr[MAXN + 1];
__device__ int   g_cursor[MAXN];
__device__ int   g_src   [MAXE];
__device__ int   g_dst   [MAXE];
__device__ int   g_ssort [MAXE];
__device__ int   g_bsum  [64];
__device__ int   g_boff  [64];
__device__ float g_stats [256];
__device__ float g_scale [128];
__device__ float g_shift [128];
__device__ int   g_is64;

// ---------------- PTX helpers ----------------
__device__ __forceinline__ uint32_t s2u(const void* p) {
    uint32_t a;
    asm("{ .reg .u64 t; cvta.to.shared.u64 t, %1; cvt.u32.u64 %0, t; }"
        : "=r"(a) : "l"(p));
    return a;
}

__device__ __forceinline__ void ldm4(uint32_t* r, uint32_t addr) {
    asm volatile("ldmatrix.sync.aligned.m8n8.x4.shared.b16 {%0,%1,%2,%3}, [%4];"
        : "=r"(r[0]), "=r"(r[1]), "=r"(r[2]), "=r"(r[3]) : "r"(addr));
}

__device__ __forceinline__ void mma16816(float* d, const uint32_t* a,
                                         uint32_t b0, uint32_t b1) {
    asm volatile(
        "mma.sync.aligned.m16n8k16.row.col.f32.bf16.bf16.f32 "
        "{%0,%1,%2,%3}, {%4,%5,%6,%7}, {%8,%9}, {%0,%1,%2,%3};"
        : "+f"(d[0]), "+f"(d[1]), "+f"(d[2]), "+f"(d[3])
        : "r"(a[0]), "r"(a[1]), "r"(a[2]), "r"(a[3]), "r"(b0), "r"(b1));
}

__device__ __forceinline__ uint32_t pkbf(float a, float b) {
    __nv_bfloat162 h = __halves2bfloat162(__float2bfloat16(a), __float2bfloat16(b));
    return *(uint32_t*)&h;
}

// smem layout for GEMM (bytes)
#define SM_A  0            // A: 2 halves x 4 k-sections x [128r][64c bf16] = 131072
#define SM_W  131072       // W chunk: 2 halves x 2 k-sections x [128n][64k] = 65536
#define SM_TOTAL 196608

// ---------------- edge preprocessing ----------------
__global__ void k_detect(const void* __restrict__ ei, int E) {
    if (threadIdx.x == 0) {
        const int* p = (const int*)ei;
        int m = E < 64 ? E : 64, is64 = 1;
        for (int i = 0; i < m; i++)
            if (p[2 * i + 1] != 0) { is64 = 0; break; }
        g_is64 = is64;
    }
}

__global__ void k_zero_build(int n) {
    int i = blockIdx.x * blockDim.x + threadIdx.x;
    if (i < n) { g_deg[i] = 0; g_cursor[i] = 0; }
    if (i < 256) g_stats[i] = 0.f;
}

__global__ void k_edges(const void* __restrict__ ei, int E) {
    int i = blockIdx.x * blockDim.x + threadIdx.x;
    if (i >= E) return;
    int s, d;
    if (g_is64) {
        const long long* q = (const long long*)ei;
        s = (int)q[i]; d = (int)q[E + i];
    } else {
        const int* q = (const int*)ei;
        s = q[i]; d = q[E + i];
    }
    g_src[i] = s; g_dst[i] = d;
    atomicAdd(&g_deg[d], 1);
}

// ---------------- multi-block scan: deg -> rowptr ----------------
__global__ void k_scan1(int n) {
    __shared__ int warpsums[8];
    int tid = threadIdx.x, lane = tid & 31, wid = tid >> 5;
    int i0 = blockIdx.x * 2048 + tid * 8;
    int v[8], tot = 0;
    #pragma unroll
    for (int j = 0; j < 8; j++) {
        v[j] = (i0 + j < n) ? g_deg[i0 + j] : 0;
        tot += v[j];
    }
    int x = tot;
    #pragma unroll
    for (int off = 1; off < 32; off <<= 1) {
        int t = __shfl_up_sync(0xffffffffu, x, off);
        if (lane >= off) x += t;
    }
    if (lane == 31) warpsums[wid] = x;
    __syncthreads();
    if (wid == 0) {
        int w = (lane < 8) ? warpsums[lane] : 0;
        #pragma unroll
        for (int off = 1; off < 8; off <<= 1) {
            int t = __shfl_up_sync(0xffffffffu, w, off);
            if (lane >= off) w += t;
        }
        if (lane < 8) warpsums[lane] = w;
    }
    __syncthreads();
    int wpref = (wid > 0) ? warpsums[wid - 1] : 0;
    int run = wpref + (x - tot);
    #pragma unroll
    for (int j = 0; j < 8; j++) {
        run += v[j];
        if (i0 + j < n) g_rowptr[i0 + j + 1] = run;
    }
    if (tid == 0) g_bsum[blockIdx.x] = warpsums[7];
}

__global__ void k_scan2(int nb) {
    int lane = threadIdx.x;
    int a = (2 * lane     < nb) ? g_bsum[2 * lane]     : 0;
    int b = (2 * lane + 1 < nb) ? g_bsum[2 * lane + 1] : 0;
    int t = a + b;
    int x = t;
    #pragma unroll
    for (int off = 1; off < 32; off <<= 1) {
        int u = __shfl_up_sync(0xffffffffu, x, off);
        if (lane >= off) x += u;
    }
    int excl = x - t;
    if (2 * lane     < nb) g_boff[2 * lane]     = excl;
    if (2 * lane + 1 < nb) g_boff[2 * lane + 1] = excl + a;
}

__global__ void k_scan3(int n) {
    int i = blockIdx.x * blockDim.x + threadIdx.x;
    if (i == 0) g_rowptr[0] = 0;
    if (i < n) g_rowptr[i + 1] += g_boff[i >> 11];
}

__global__ void k_fill(int E) {
    int i = blockIdx.x * blockDim.x + threadIdx.x;
    if (i >= E) return;
    int d = g_dst[i];
    int p = g_rowptr[d] + atomicAdd(&g_cursor[d], 1);
    g_ssort[p] = g_src[i];
}

__global__ void k_prep_w(const float* __restrict__ Wl,
                         const float* __restrict__ Wr, int layer) {
    int i = blockIdx.x * blockDim.x + threadIdx.x;   // 128*256
    if (i >= 128 * 256) return;
    int nn = i >> 8, k = i & 255;
    float v = (k < 128) ? __ldg(&Wl[k * 128 + nn]) : __ldg(&Wr[(k - 128) * 128 + nn]);
    __nv_bfloat16 h = __float2bfloat16(v);
    g_wth[layer][i] = h;
    g_wtl[layer][i] = __float2bfloat16(v - __bfloat162float(h));
}

// ---------------- x -> fp16 copy (gather source for layer 0) ----------------
__global__ void k_tohalf_x(const float* __restrict__ x, int n) {
    int i = blockIdx.x * blockDim.x + threadIdx.x;   // n*32 float4 groups
    if (i >= n * 32) return;
    float4 v = __ldg(&((const float4*)x)[i]);
    uint2 o;
    __half2 a = __floats2half2_rn(v.x, v.y);
    __half2 b = __floats2half2_rn(v.z, v.w);
    o.x = *(uint32_t*)&a; o.y = *(uint32_t*)&b;
    ((uint2*)g_hhalf)[0];  // no-op keep types
    ((uint2*)g_xhalf)[i] = o;
}

// ---------------- BN+ReLU -> fp16 (gather source for layer 1) ----------------
__global__ void k_apply_h(int n) {
    int i = blockIdx.x * blockDim.x + threadIdx.x;   // n*32 float4 groups
    if (i >= n * 32) return;
    int cg = i & 31;
    float4 v  = ((const float4*)g_hpre)[i];
    float4 sc = ((const float4*)g_scale)[cg];
    float4 sh = ((const float4*)g_shift)[cg];
    v.x = fmaxf(v.x * sc.x + sh.x, 0.f);
    v.y = fmaxf(v.y * sc.y + sh.y, 0.f);
    v.z = fmaxf(v.z * sc.z + sh.z, 0.f);
    v.w = fmaxf(v.w * sc.w + sh.w, 0.f);
    uint2 o;
    __half2 a = __floats2half2_rn(v.x, v.y);
    __half2 b = __floats2half2_rn(v.z, v.w);
    o.x = *(uint32_t*)&a; o.y = *(uint32_t*)&b;
    ((uint2*)g_hhalf)[i] = o;
}

// ---------------- aggregation: warp per node, fp16 gather, fp32 mean ----------
__global__ void k_aggregate(int layer, int n) {
    int gw   = (blockIdx.x * blockDim.x + threadIdx.x) >> 5;
    int lane = threadIdx.x & 31;
    if (gw >= n) return;
    const uint2* in2 = (const uint2*)(layer ? g_hhalf : g_xhalf);
    int e0 = g_rowptr[gw], e1 = g_rowptr[gw + 1];
    float4 acc = make_float4(0.f, 0.f, 0.f, 0.f);
    #pragma unroll 4
    for (int e = e0; e < e1; e++) {
        int s = __ldg(&g_ssort[e]);
        uint2 p = __ldg(&in2[s * 32 + lane]);
        float2 ab = __half22float2(*(__half2*)&p.x);
        float2 cd = __half22float2(*(__half2*)&p.y);
        acc.x += ab.x; acc.y += ab.y; acc.z += cd.x; acc.w += cd.y;
    }
    float inv = 1.0f / fmaxf((float)(e1 - e0), 1.0f);
    acc.x *= inv; acc.y *= inv; acc.z *= inv; acc.w *= inv;
    ((float4*)g_agg)[gw * 32 + lane] = acc;
}

// ---------------- mma.sync GEMM + fused BN column stats ----------------
// Block tile: 128 rows x 128 cols, K=256 in 2 W-chunks of 128.
// A loaded fp32 ([agg | self]), split to bf16 hi/lo inline; layer-1 self path
// applies BN+ReLU (exact fp32) first. Products hi*hi + hi*lo + lo*hi.
__global__ void __launch_bounds__(256, 1)
k_gemm_mma(int layer, int use_x, const float* __restrict__ xext,
           const float* __restrict__ bias, int n) {
    extern __shared__ char smem[];
    uint32_t sb = s2u(smem);
    int tid  = threadIdx.x;
    int wid  = tid >> 5;
    int lane = tid & 31;
    int row0 = blockIdx.x * 128;

    // ---- load A tile fp32, split to hi/lo bf16 in smem: 8192 float4 ----
    const float4* agg4 = (const float4*)g_agg;
    for (int i = tid; i < 8192; i += 256) {
        int r  = i >> 6;                 // 0..127
        int c4 = i & 63;                 // float4 index over 256 cols
        int c0 = c4 * 4;
        int row = row0 + r;
        float4 v = make_float4(0.f, 0.f, 0.f, 0.f);
        if (row < n) {
            if (c0 < 128) {
                v = __ldg(&agg4[row * 32 + c4]);
            } else if (use_x) {
                v = __ldg(&((const float4*)xext)[row * 32 + (c4 - 32)]);
            } else {
                int cc = c0 - 128;
                v = *(const float4*)(g_hpre + (size_t)row * 128 + cc);
                float4 sc = *(const float4*)(g_scale + cc);
                float4 sh = *(const float4*)(g_shift + cc);
                v.x = fmaxf(v.x * sc.x + sh.x, 0.f);
                v.y = fmaxf(v.y * sc.y + sh.y, 0.f);
                v.z = fmaxf(v.z * sc.z + sh.z, 0.f);
                v.w = fmaxf(v.w * sc.w + sh.w, 0.f);
            }
        }
        float hx = __bfloat162float(__float2bfloat16(v.x));
        float hy = __bfloat162float(__float2bfloat16(v.y));
        float hz = __bfloat162float(__float2bfloat16(v.z));
        float hw = __bfloat162float(__float2bfloat16(v.w));
        uint2 hi = make_uint2(pkbf(v.x, v.y), pkbf(v.z, v.w));
        uint2 lo = make_uint2(pkbf(v.x - hx, v.y - hy), pkbf(v.z - hz, v.w - hw));
        int s   = c0 >> 6;
        int cc  = c0 & 63;
        int gin = cc >> 3;               // 16B granule
        int hg  = (cc >> 2) & 1;         // which 8B half
        char* dst = smem + SM_A + s * 16384 + r * 128 +
                    ((gin ^ (r & 7)) * 16) + hg * 8;
        *(uint2*)dst = hi;
        *(uint2*)(dst + 65536) = lo;
    }

    int wm = wid >> 1, wn = wid & 1;
    int m0 = wm * 32, n0 = wn * 64;
    float acc[2][8][4];
    #pragma unroll
    for (int mf = 0; mf < 2; mf++)
        #pragma unroll
        for (int nf = 0; nf < 8; nf++)
            #pragma unroll
            for (int q = 0; q < 4; q++) acc[mf][nf][q] = 0.f;

    int lx    = lane & 7;
    int aRow  = lane & 15;
    int aKoff = lane >> 4;
    int wRow  = (lane & 7) + ((lane >> 4) << 3);
    int wKoff = (lane >> 3) & 1;

    const __nv_bfloat16* wth = g_wth[layer];
    const __nv_bfloat16* wtl = g_wtl[layer];

    #pragma unroll 1
    for (int kc = 0; kc < 2; kc++) {
        __syncthreads();
        // ---- load W chunk (hi + lo), 4096 uint4 ----
        for (int i = tid; i < 4096; i += 256) {
            int half = i >> 11;
            int j = i & 2047;
            int r  = j >> 4;
            int kin = (j & 15) * 8;
            int s2 = kin >> 6;
            int gin = (kin >> 3) & 7;
            const __nv_bfloat16* base = half ? wtl : wth;
            uint4 v = __ldg((const uint4*)(base + (size_t)r * 256 + kc * 128 + kin));
            *(uint4*)(smem + SM_W + half * 32768 + s2 * 16384 + r * 128 +
                      ((gin ^ (r & 7)) * 16)) = v;
        }
        __syncthreads();

        #pragma unroll 1
        for (int ksl = 0; ksl < 8; ksl++) {
            int ks   = kc * 8 + ksl;
            int sA   = ks >> 2;
            int kgA  = (ks & 3) * 2 + aKoff;
            int s2   = ksl >> 2;
            int kgW  = (ksl & 3) * 2 + wKoff;

            #pragma unroll
            for (int ah = 0; ah < 2; ah++) {
                uint32_t af[2][4];
                #pragma unroll
                for (int mf = 0; mf < 2; mf++) {
                    int r = m0 + mf * 16 + aRow;
                    uint32_t addr = sb + SM_A + ah * 65536 + sA * 16384 +
                                    r * 128 + ((kgA ^ lx) * 16);
                    ldm4(af[mf], addr);
                }
                int nwh = (ah == 0) ? 2 : 1;        // Ah*{Wh,Wl}, Al*Wh
                #pragma unroll
                for (int wh = 0; wh < 2; wh++) {
                    if (wh >= nwh) break;
                    #pragma unroll
                    for (int np = 0; np < 4; np++) {
                        uint32_t wf[4];
                        int r = n0 + np * 16 + wRow;
                        uint32_t addr = sb + SM_W + wh * 32768 + s2 * 16384 +
                                        r * 128 + ((kgW ^ lx) * 16);
                        ldm4(wf, addr);
                        #pragma unroll
                        for (int mf = 0; mf < 2; mf++) {
                            mma16816(acc[mf][np * 2],     af[mf], wf[0], wf[1]);
                            mma16816(acc[mf][np * 2 + 1], af[mf], wf[2], wf[3]);
                        }
                    }
                }
            }
        }
    }

    // ---- epilogue: add bias, store fp32, fused BN column stats ----
    #pragma unroll
    for (int nf = 0; nf < 8; nf++) {
        int col = n0 + nf * 8 + (lane & 3) * 2;
        float bx = __ldg(&bias[col]), by = __ldg(&bias[col + 1]);
        float s0 = 0.f, q0 = 0.f, s1 = 0.f, q1 = 0.f;
        #pragma unroll
        for (int mf = 0; mf < 2; mf++) {
            int row = row0 + m0 + mf * 16 + (lane >> 2);
            if (row < n) {
                float a = acc[mf][nf][0] + bx, b = acc[mf][nf][1] + by;
                *(float2*)(g_hpre + (size_t)row * 128 + col) = make_float2(a, b);
                s0 += a; q0 += a * a; s1 += b; q1 += b * b;
            }
            if (row + 8 < n) {
                float a = acc[mf][nf][2] + bx, b = acc[mf][nf][3] + by;
                *(float2*)(g_hpre + (size_t)(row + 8) * 128 + col) = make_float2(a, b);
                s0 += a; q0 += a * a; s1 += b; q1 += b * b;
            }
        }
        #pragma unroll
        for (int off = 4; off < 32; off <<= 1) {
            s0 += __shfl_xor_sync(0xffffffffu, s0, off);
            q0 += __shfl_xor_sync(0xffffffffu, q0, off);
            s1 += __shfl_xor_sync(0xffffffffu, s1, off);
            q1 += __shfl_xor_sync(0xffffffffu, q1, off);
        }
        if (lane < 4) {
            int c = n0 + nf * 8 + lane * 2;
            atomicAdd(&g_stats[c],       s0);
            atomicAdd(&g_stats[128 + c], q0);
            atomicAdd(&g_stats[c + 1],       s1);
            atomicAdd(&g_stats[128 + c + 1], q1);
        }
    }
}

// ---------------- BatchNorm finalize (self-zeroing stats) ----------------
__global__ void k_finalize(const float* __restrict__ gamma,
                           const float* __restrict__ beta, int n) {
    int t = threadIdx.x;
    float invn = 1.0f / (float)n;
    float mu  = g_stats[t] * invn;
    float var = fmaxf(g_stats[128 + t] * invn - mu * mu, 0.f);
    g_stats[t] = 0.f;
    g_stats[128 + t] = 0.f;
    float rs = rsqrtf(var + 1e-5f);
    float sc = __ldg(&gamma[t]) * rs;
    g_scale[t] = sc;
    g_shift[t] = __ldg(&beta[t]) - mu * sc;
}

// BN apply + ReLU + [128,2] linear -> d_out
__global__ void k_apply_out(const float* __restrict__ Wout,
                            const float* __restrict__ bout,
                            float* __restrict__ out, int n) {
    int gw   = (blockIdx.x * blockDim.x + threadIdx.x) >> 5;
    int lane = threadIdx.x & 31;
    if (gw >= n) return;
    float4 v  = ((const float4*)g_hpre)[gw * 32 + lane];
    float4 sc = ((const float4*)g_scale)[lane];
    float4 sh = ((const float4*)g_shift)[lane];
    v.x = fmaxf(v.x * sc.x + sh.x, 0.f);
    v.y = fmaxf(v.y * sc.y + sh.y, 0.f);
    v.z = fmaxf(v.z * sc.z + sh.z, 0.f);
    v.w = fmaxf(v.w * sc.w + sh.w, 0.f);
    const float4* W4 = (const float4*)Wout;
    float4 wa = __ldg(&W4[lane * 2]);
    float4 wb = __ldg(&W4[lane * 2 + 1]);
    float s0 = v.x * wa.x + v.y * wa.z + v.z * wb.x + v.w * wb.z;
    float s1 = v.x * wa.y + v.y * wa.w + v.z * wb.y + v.w * wb.w;
    #pragma unroll
    for (int off = 16; off; off >>= 1) {
        s0 += __shfl_xor_sync(0xffffffffu, s0, off);
        s1 += __shfl_xor_sync(0xffffffffu, s1, off);
    }
    if (lane == 0) {
        out[gw * 2 + 0] = s0 + __ldg(&bout[0]);
        out[gw * 2 + 1] = s1 + __ldg(&bout[1]);
    }
}

// ---------------------------------------------------------------------------
extern "C" void kernel_launch(void* const* d_in, const int* in_sizes, int n_in,
                              void* d_out, int out_size) {
    const float* x    = (const float*)d_in[0];
    const void*  ei   = d_in[1];
    const float* Wl0  = (const float*)d_in[2];
    const float* Wr0  = (const float*)d_in[3];
    const float* b0   = (const float*)d_in[4];
    const float* gm0  = (const float*)d_in[5];
    const float* be0  = (const float*)d_in[6];
    const float* Wl1  = (const float*)d_in[7];
    const float* Wr1  = (const float*)d_in[8];
    const float* b1   = (const float*)d_in[9];
    const float* gm1  = (const float*)d_in[10];
    const float* be1  = (const float*)d_in[11];
    const float* Wout = (const float*)d_in[12];
    const float* bout = (const float*)d_in[13];
    float* out = (float*)d_out;

    int E = in_sizes[1] / 2;  if (E > MAXE) E = MAXE;
    int n = out_size / 2;     if (n > MAXN) n = MAXN;

    cudaFuncSetAttribute(k_gemm_mma,
        cudaFuncAttributeMaxDynamicSharedMemorySize, SM_TOTAL);

    int eb = (E + 255) / 256;
    int nb = (n + 255) / 256;
    int ab = (n * 32 + 255) / 256;          // warp-per-node / float4-per-thread
    int gb = (n + 127) / 128;
    int sb = (n + 2047) / 2048;             // scan blocks

    // --- CSR build + weight/x prep ---
    k_detect    <<<1, 32>>>(ei, E);
    k_zero_build<<<nb, 256>>>(n);
    k_edges     <<<eb, 256>>>(ei, E);
    k_scan1     <<<sb, 256>>>(n);
    k_scan2     <<<1, 32>>>(sb);
    k_scan3     <<<nb, 256>>>(n);
    k_fill      <<<eb, 256>>>(E);
    k_tohalf_x  <<<ab, 256>>>(x, n);
    k_prep_w    <<<128, 256>>>(Wl0, Wr0, 0);
    k_prep_w    <<<128, 256>>>(Wl1, Wr1, 1);

    // --- layer 0 ---
    k_aggregate <<<ab, 256>>>(0, n);
    k_gemm_mma  <<<gb, 256, SM_TOTAL>>>(0, 1, x, b0, n);
    k_finalize  <<<1, 128>>>(gm0, be0, n);
    k_apply_h   <<<ab, 256>>>(n);

    // --- layer 1 ---
    k_aggregate <<<ab, 256>>>(1, n);
    k_gemm_mma  <<<gb, 256, SM_TOTAL>>>(1, 0, nullptr, b1, n);
    k_finalize  <<<1, 128>>>(gm1, be1, n);

    // --- fused BN+ReLU+Linear[128->2] -> d_out ---
    k_apply_out <<<ab, 256>>>(Wout, bout, out, n);
}

// round 11
// speedup vs baseline: 1.0812x; 1.0165x over previous
#include <cuda_runtime.h>
#include <cuda_bf16.h>
#include <cuda_fp16.h>
#include <cstdint>

// ---------------------------------------------------------------------------
// GraphSAGE: 2x (SAGEConv -> BN(train) -> ReLU) -> Linear[128->2]
//  11-launch pipeline:
//   init (detect+zero) -> edges(hist) -> scan1 -> scan3(inline scan2)
//   -> prep (fill + x->fp16 + W split/transpose)
//   -> [agg -> gemm(+stats) ] x2 with apply_h between, apply_out at end.
//  BN finalize is computed inline per consumer block from raw stats
//  (ping-pong stats0/stats1), eliminating 1-block finalize kernels.
// ---------------------------------------------------------------------------

#define MAXN 50000
#define MAXE 1048576

__device__ float g_hpre[MAXN * 128];
__device__ float g_agg [MAXN * 128];
__device__ __half g_xhalf[MAXN * 128];   // fp16 x (gather source, L0)
__device__ __half g_hhalf[MAXN * 128];   // fp16 relu(bn(hpre)) (gather source, L1)
__device__ __nv_bfloat16 g_wth [2][128 * 256];   // [layer][n][k] transposed hi
__device__ __nv_bfloat16 g_wtl [2][128 * 256];   // lo
__device__ int   g_deg   [MAXN];
__device__ int   g_rowptr[MAXN + 1];
__device__ int   g_cursor[MAXN];
__device__ int   g_src   [MAXE];
__device__ int   g_dst   [MAXE];
__device__ int   g_ssort [MAXE];
__device__ int   g_bsum  [64];
__device__ float g_stats0[256];          // layer-0 col sums / sumsq
__device__ float g_stats1[256];          // layer-1
__device__ int   g_is64;

// ---------------- PTX helpers ----------------
__device__ __forceinline__ uint32_t s2u(const void* p) {
    uint32_t a;
    asm("{ .reg .u64 t; cvta.to.shared.u64 t, %1; cvt.u32.u64 %0, t; }"
        : "=r"(a) : "l"(p));
    return a;
}

__device__ __forceinline__ void ldm4(uint32_t* r, uint32_t addr) {
    asm volatile("ldmatrix.sync.aligned.m8n8.x4.shared.b16 {%0,%1,%2,%3}, [%4];"
        : "=r"(r[0]), "=r"(r[1]), "=r"(r[2]), "=r"(r[3]) : "r"(addr));
}

__device__ __forceinline__ void mma16816(float* d, const uint32_t* a,
                                         uint32_t b0, uint32_t b1) {
    asm volatile(
        "mma.sync.aligned.m16n8k16.row.col.f32.bf16.bf16.f32 "
        "{%0,%1,%2,%3}, {%4,%5,%6,%7}, {%8,%9}, {%0,%1,%2,%3};"
        : "+f"(d[0]), "+f"(d[1]), "+f"(d[2]), "+f"(d[3])
        : "r"(a[0]), "r"(a[1]), "r"(a[2]), "r"(a[3]), "r"(b0), "r"(b1));
}

__device__ __forceinline__ uint32_t pkbf(float a, float b) {
    __nv_bfloat162 h = __halves2bfloat162(__float2bfloat16(a), __float2bfloat16(b));
    return *(uint32_t*)&h;
}

// compute BN scale/shift into smem from raw stats (128 threads participate)
__device__ __forceinline__ void finalize_smem(
        const float* __restrict__ stats, const float* __restrict__ gamma,
        const float* __restrict__ beta, int n, float* s_sc, float* s_sh, int tid) {
    if (tid < 128) {
        float invn = 1.0f / (float)n;
        float mu  = stats[tid] * invn;
        float var = fmaxf(stats[128 + tid] * invn - mu * mu, 0.f);
        float rs  = rsqrtf(var + 1e-5f);
        float sc  = __ldg(&gamma[tid]) * rs;
        s_sc[tid] = sc;
        s_sh[tid] = __ldg(&beta[tid]) - mu * sc;
    }
    __syncthreads();
}

// smem layout for GEMM (bytes, dynamic)
#define SM_A  0            // A: 2 halves x 4 k-sections x [128r][64c bf16] = 131072
#define SM_W  131072       // W chunk: 2 halves x 2 k-sections x [128n][64k] = 65536
#define SM_TOTAL 196608

// ---------------- init: dtype detect + zero counters/stats ----------------
__global__ void k_init(const void* __restrict__ ei, int E, int n) {
    int i = blockIdx.x * blockDim.x + threadIdx.x;
    if (i == 0) {
        const int* p = (const int*)ei;
        int m = E < 64 ? E : 64, is64 = 1;
        for (int j = 0; j < m; j++)
            if (p[2 * j + 1] != 0) { is64 = 0; break; }
        g_is64 = is64;
    }
    if (i < n) { g_deg[i] = 0; g_cursor[i] = 0; }
    if (i < 256) { g_stats0[i] = 0.f; g_stats1[i] = 0.f; }
}

__global__ void k_edges(const void* __restrict__ ei, int E) {
    int i = blockIdx.x * blockDim.x + threadIdx.x;
    if (i >= E) return;
    int s, d;
    if (g_is64) {
        const long long* q = (const long long*)ei;
        s = (int)q[i]; d = (int)q[E + i];
    } else {
        const int* q = (const int*)ei;
        s = q[i]; d = q[E + i];
    }
    g_src[i] = s; g_dst[i] = d;
    atomicAdd(&g_deg[d], 1);
}

// ---------------- scan pass 1: per-2048-chunk inclusive scan ----------------
__global__ void k_scan1(int n) {
    __shared__ int warpsums[8];
    int tid = threadIdx.x, lane = tid & 31, wid = tid >> 5;
    int i0 = blockIdx.x * 2048 + tid * 8;
    int v[8], tot = 0;
    #pragma unroll
    for (int j = 0; j < 8; j++) {
        v[j] = (i0 + j < n) ? g_deg[i0 + j] : 0;
        tot += v[j];
    }
    int x = tot;
    #pragma unroll
    for (int off = 1; off < 32; off <<= 1) {
        int t = __shfl_up_sync(0xffffffffu, x, off);
        if (lane >= off) x += t;
    }
    if (lane == 31) warpsums[wid] = x;
    __syncthreads();
    if (wid == 0) {
        int w = (lane < 8) ? warpsums[lane] : 0;
        #pragma unroll
        for (int off = 1; off < 8; off <<= 1) {
            int t = __shfl_up_sync(0xffffffffu, w, off);
            if (lane >= off) w += t;
        }
        if (lane < 8) warpsums[lane] = w;
    }
    __syncthreads();
    int wpref = (wid > 0) ? warpsums[wid - 1] : 0;
    int run = wpref + (x - tot);
    #pragma unroll
    for (int j = 0; j < 8; j++) {
        run += v[j];
        if (i0 + j < n) g_rowptr[i0 + j + 1] = run;
    }
    if (tid == 0) g_bsum[blockIdx.x] = warpsums[7];
}

// ---------------- scan pass 2+3 fused: per-block reduce bsum prefix, add ----
__global__ void k_scan3(int n) {
    __shared__ int sh_off;
    int tid = threadIdx.x;
    int chunk = blockIdx.x >> 3;         // which 2048-chunk this 256-block is in
    if (tid < 32) {
        int v = (tid < chunk) ? g_bsum[tid] : 0;   // chunk <= 24 < 32 for MAXN
        #pragma unroll
        for (int off = 16; off; off >>= 1)
            v += __shfl_xor_sync(0xffffffffu, v, off);
        if (tid == 0) sh_off = v;
    }
    __syncthreads();
    int i = blockIdx.x * 256 + tid;
    if (i == 0) g_rowptr[0] = 0;
    if (i < n) g_rowptr[i + 1] += sh_off;
}

// ---------------- prep: edge fill + x->fp16 + weight split/transpose ----------
__global__ void k_prep(const float* __restrict__ x,
                       const float* __restrict__ Wl0, const float* __restrict__ Wr0,
                       const float* __restrict__ Wl1, const float* __restrict__ Wr1,
                       int E, int n) {
    int i = blockIdx.x * blockDim.x + threadIdx.x;
    if (i < E) {
        int d = g_dst[i];
        int p = g_rowptr[d] + atomicAdd(&g_cursor[d], 1);
        g_ssort[p] = g_src[i];
        return;
    }
    i -= E;
    int nx = n * 32;
    if (i < nx) {                         // x -> fp16, float4 group per thread
        float4 v = __ldg(&((const float4*)x)[i]);
        __half2 a = __floats2half2_rn(v.x, v.y);
        __half2 b = __floats2half2_rn(v.z, v.w);
        uint2 o = make_uint2(*(uint32_t*)&a, *(uint32_t*)&b);
        ((uint2*)g_xhalf)[i] = o;
        return;
    }
    i -= nx;
    if (i < 65536) {                      // weight transpose + hi/lo split
        int layer = i >> 15;
        int t = i & 32767;                // 128*256
        int nn = t >> 8, k = t & 255;
        const float* Wl = layer ? Wl1 : Wl0;
        const float* Wr = layer ? Wr1 : Wr0;
        float v = (k < 128) ? __ldg(&Wl[k * 128 + nn])
                            : __ldg(&Wr[(k - 128) * 128 + nn]);
        __nv_bfloat16 h = __float2bfloat16(v);
        g_wth[layer][t] = h;
        g_wtl[layer][t] = __float2bfloat16(v - __bfloat162float(h));
    }
}

// ---------------- aggregation: half-warp (16 lanes) per node ----------------
// fp16 row = 256B = 16 lanes x uint4. Two independent nodes per warp -> 2x MLP.
__global__ void k_aggregate(int layer, int n) {
    int node = (blockIdx.x * blockDim.x + threadIdx.x) >> 4;
    int lane = threadIdx.x & 15;
    if (node >= n) return;
    const uint4* in4 = (const uint4*)(layer ? g_hhalf : g_xhalf);
    int e0 = g_rowptr[node], e1 = g_rowptr[node + 1];
    float acc[8] = {0.f, 0.f, 0.f, 0.f, 0.f, 0.f, 0.f, 0.f};
    #pragma unroll 4
    for (int e = e0; e < e1; e++) {
        int s = __ldg(&g_ssort[e]);
        uint4 p = __ldg(&in4[s * 16 + lane]);
        const __half2* h = (const __half2*)&p;
        #pragma unroll
        for (int q = 0; q < 4; q++) {
            float2 f = __half22float2(h[q]);
            acc[2 * q]     += f.x;
            acc[2 * q + 1] += f.y;
        }
    }
    float inv = 1.0f / fmaxf((float)(e1 - e0), 1.0f);
    float4* out = (float4*)(g_agg + (size_t)node * 128 + lane * 8);
    out[0] = make_float4(acc[0] * inv, acc[1] * inv, acc[2] * inv, acc[3] * inv);
    out[1] = make_float4(acc[4] * inv, acc[5] * inv, acc[6] * inv, acc[7] * inv);
}

// ---------------- mma.sync GEMM + fused BN column stats ----------------
// Block tile: 128 rows x 128 cols, K=256 in 2 W-chunks of 128.
// A loaded fp32 ([agg | self]), split to bf16 hi/lo inline; layer-1 self path
// applies BN+ReLU (scale/shift computed in-block from g_stats0).
// Epilogue accumulates col sums/sumsq into g_stats<layer>.
__global__ void __launch_bounds__(256, 1)
k_gemm_mma(int layer, int use_x, const float* __restrict__ xext,
           const float* __restrict__ bias,
           const float* __restrict__ gamma_prev,
           const float* __restrict__ beta_prev, int n) {
    extern __shared__ char smem[];
    __shared__ __align__(16) float s_sc[128];
    __shared__ __align__(16) float s_sh[128];
    uint32_t sb = s2u(smem);
    int tid  = threadIdx.x;
    int wid  = tid >> 5;
    int lane = tid & 31;
    int row0 = blockIdx.x * 128;
    float* stats_out = layer ? g_stats1 : g_stats0;

    if (!use_x)
        finalize_smem(g_stats0, gamma_prev, beta_prev, n, s_sc, s_sh, tid);

    // ---- load A tile fp32, split to hi/lo bf16 in smem: 8192 float4 ----
    const float4* agg4 = (const float4*)g_agg;
    for (int i = tid; i < 8192; i += 256) {
        int r  = i >> 6;                 // 0..127
        int c4 = i & 63;                 // float4 index over 256 cols
        int c0 = c4 * 4;
        int row = row0 + r;
        float4 v = make_float4(0.f, 0.f, 0.f, 0.f);
        if (row < n) {
            if (c0 < 128) {
                v = __ldg(&agg4[row * 32 + c4]);
            } else if (use_x) {
                v = __ldg(&((const float4*)xext)[row * 32 + (c4 - 32)]);
            } else {
                int cc = c0 - 128;
                v = *(const float4*)(g_hpre + (size_t)row * 128 + cc);
                float4 sc = *(const float4*)(s_sc + cc);
                float4 sh = *(const float4*)(s_sh + cc);
                v.x = fmaxf(v.x * sc.x + sh.x, 0.f);
                v.y = fmaxf(v.y * sc.y + sh.y, 0.f);
                v.z = fmaxf(v.z * sc.z + sh.z, 0.f);
                v.w = fmaxf(v.w * sc.w + sh.w, 0.f);
            }
        }
        float hx = __bfloat162float(__float2bfloat16(v.x));
        float hy = __bfloat162float(__float2bfloat16(v.y));
        float hz = __bfloat162float(__float2bfloat16(v.z));
        float hw = __bfloat162float(__float2bfloat16(v.w));
        uint2 hi = make_uint2(pkbf(v.x, v.y), pkbf(v.z, v.w));
        uint2 lo = make_uint2(pkbf(v.x - hx, v.y - hy), pkbf(v.z - hz, v.w - hw));
        int s   = c0 >> 6;
        int cc  = c0 & 63;
        int gin = cc >> 3;               // 16B granule
        int hg  = (cc >> 2) & 1;         // which 8B half
        char* dst = smem + SM_A + s * 16384 + r * 128 +
                    ((gin ^ (r & 7)) * 16) + hg * 8;
        *(uint2*)dst = hi;
        *(uint2*)(dst + 65536) = lo;
    }

    int wm = wid >> 1, wn = wid & 1;
    int m0 = wm * 32, n0 = wn * 64;
    float acc[2][8][4];
    #pragma unroll
    for (int mf = 0; mf < 2; mf++)
        #pragma unroll
        for (int nf = 0; nf < 8; nf++)
            #pragma unroll
            for (int q = 0; q < 4; q++) acc[mf][nf][q] = 0.f;

    int lx    = lane & 7;
    int aRow  = lane & 15;
    int aKoff = lane >> 4;
    int wRow  = (lane & 7) + ((lane >> 4) << 3);
    int wKoff = (lane >> 3) & 1;

    const __nv_bfloat16* wth = g_wth[layer];
    const __nv_bfloat16* wtl = g_wtl[layer];

    #pragma unroll 1
    for (int kc = 0; kc < 2; kc++) {
        __syncthreads();
        // ---- load W chunk (hi + lo), 4096 uint4 ----
        for (int i = tid; i < 4096; i += 256) {
            int half = i >> 11;
            int j = i & 2047;
            int r  = j >> 4;
            int kin = (j & 15) * 8;
            int s2 = kin >> 6;
            int gin = (kin >> 3) & 7;
            const __nv_bfloat16* base = half ? wtl : wth;
            uint4 v = __ldg((const uint4*)(base + (size_t)r * 256 + kc * 128 + kin));
            *(uint4*)(smem + SM_W + half * 32768 + s2 * 16384 + r * 128 +
                      ((gin ^ (r & 7)) * 16)) = v;
        }
        __syncthreads();

        #pragma unroll 1
        for (int ksl = 0; ksl < 8; ksl++) {
            int ks   = kc * 8 + ksl;
            int sA   = ks >> 2;
            int kgA  = (ks & 3) * 2 + aKoff;
            int s2   = ksl >> 2;
            int kgW  = (ksl & 3) * 2 + wKoff;

            #pragma unroll
            for (int ah = 0; ah < 2; ah++) {
                uint32_t af[2][4];
                #pragma unroll
                for (int mf = 0; mf < 2; mf++) {
                    int r = m0 + mf * 16 + aRow;
                    uint32_t addr = sb + SM_A + ah * 65536 + sA * 16384 +
                                    r * 128 + ((kgA ^ lx) * 16);
                    ldm4(af[mf], addr);
                }
                int nwh = (ah == 0) ? 2 : 1;        // Ah*{Wh,Wl}, Al*Wh
                #pragma unroll
                for (int wh = 0; wh < 2; wh++) {
                    if (wh >= nwh) break;
                    #pragma unroll
                    for (int np = 0; np < 4; np++) {
                        uint32_t wf[4];
                        int r = n0 + np * 16 + wRow;
                        uint32_t addr = sb + SM_W + wh * 32768 + s2 * 16384 +
                                        r * 128 + ((kgW ^ lx) * 16);
                        ldm4(wf, addr);
                        #pragma unroll
                        for (int mf = 0; mf < 2; mf++) {
                            mma16816(acc[mf][np * 2],     af[mf], wf[0], wf[1]);
                            mma16816(acc[mf][np * 2 + 1], af[mf], wf[2], wf[3]);
                        }
                    }
                }
            }
        }
    }

    // ---- epilogue: add bias, store fp32, fused BN column stats ----
    #pragma unroll
    for (int nf = 0; nf < 8; nf++) {
        int col = n0 + nf * 8 + (lane & 3) * 2;
        float bx = __ldg(&bias[col]), by = __ldg(&bias[col + 1]);
        float s0 = 0.f, q0 = 0.f, s1 = 0.f, q1 = 0.f;
        #pragma unroll
        for (int mf = 0; mf < 2; mf++) {
            int row = row0 + m0 + mf * 16 + (lane >> 2);
            if (row < n) {
                float a = acc[mf][nf][0] + bx, b = acc[mf][nf][1] + by;
                *(float2*)(g_hpre + (size_t)row * 128 + col) = make_float2(a, b);
                s0 += a; q0 += a * a; s1 += b; q1 += b * b;
            }
            if (row + 8 < n) {
                float a = acc[mf][nf][2] + bx, b = acc[mf][nf][3] + by;
                *(float2*)(g_hpre + (size_t)(row + 8) * 128 + col) = make_float2(a, b);
                s0 += a; q0 += a * a; s1 += b; q1 += b * b;
            }
        }
        #pragma unroll
        for (int off = 4; off < 32; off <<= 1) {
            s0 += __shfl_xor_sync(0xffffffffu, s0, off);
            q0 += __shfl_xor_sync(0xffffffffu, q0, off);
            s1 += __shfl_xor_sync(0xffffffffu, s1, off);
            q1 += __shfl_xor_sync(0xffffffffu, q1, off);
        }
        if (lane < 4) {
            int c = n0 + nf * 8 + lane * 2;
            atomicAdd(&stats_out[c],       s0);
            atomicAdd(&stats_out[128 + c], q0);
            atomicAdd(&stats_out[c + 1],       s1);
            atomicAdd(&stats_out[128 + c + 1], q1);
        }
    }
}

// ---------------- BN+ReLU -> fp16 (gather source for layer 1) ----------------
__global__ void k_apply_h(const float* __restrict__ gamma,
                          const float* __restrict__ beta, int n) {
    __shared__ __align__(16) float s_sc[128];
    __shared__ __align__(16) float s_sh[128];
    finalize_smem(g_stats0, gamma, beta, n, s_sc, s_sh, threadIdx.x);
    int i = blockIdx.x * blockDim.x + threadIdx.x;
    if (i >= n * 32) return;
    int cg = i & 31;
    float4 v  = ((const float4*)g_hpre)[i];
    float4 sc = ((const float4*)s_sc)[cg];
    float4 sh = ((const float4*)s_sh)[cg];
    v.x = fmaxf(v.x * sc.x + sh.x, 0.f);
    v.y = fmaxf(v.y * sc.y + sh.y, 0.f);
    v.z = fmaxf(v.z * sc.z + sh.z, 0.f);
    v.w = fmaxf(v.w * sc.w + sh.w, 0.f);
    __half2 a = __floats2half2_rn(v.x, v.y);
    __half2 b = __floats2half2_rn(v.z, v.w);
    ((uint2*)g_hhalf)[i] = make_uint2(*(uint32_t*)&a, *(uint32_t*)&b);
}

// ---------------- BN apply + ReLU + [128,2] linear -> d_out ----------------
__global__ void k_apply_out(const float* __restrict__ Wout,
                            const float* __restrict__ bout,
                            const float* __restrict__ gamma,
                            const float* __restrict__ beta,
                            float* __restrict__ out, int n) {
    __shared__ __align__(16) float s_sc[128];
    __shared__ __align__(16) float s_sh[128];
    finalize_smem(g_stats1, gamma, beta, n, s_sc, s_sh, threadIdx.x);
    int gw   = (blockIdx.x * blockDim.x + threadIdx.x) >> 5;
    int lane = threadIdx.x & 31;
    if (gw >= n) return;
    float4 v  = ((const float4*)g_hpre)[gw * 32 + lane];
    float4 sc = ((const float4*)s_sc)[lane];
    float4 sh = ((const float4*)s_sh)[lane];
    v.x = fmaxf(v.x * sc.x + sh.x, 0.f);
    v.y = fmaxf(v.y * sc.y + sh.y, 0.f);
    v.z = fmaxf(v.z * sc.z + sh.z, 0.f);
    v.w = fmaxf(v.w * sc.w + sh.w, 0.f);
    const float4* W4 = (const float4*)Wout;
    float4 wa = __ldg(&W4[lane * 2]);
    float4 wb = __ldg(&W4[lane * 2 + 1]);
    float s0 = v.x * wa.x + v.y * wa.z + v.z * wb.x + v.w * wb.z;
    float s1 = v.x * wa.y + v.y * wa.w + v.z * wb.y + v.w * wb.w;
    #pragma unroll
    for (int off = 16; off; off >>= 1) {
        s0 += __shfl_xor_sync(0xffffffffu, s0, off);
        s1 += __shfl_xor_sync(0xffffffffu, s1, off);
    }
    if (lane == 0) {
        out[gw * 2 + 0] = s0 + __ldg(&bout[0]);
        out[gw * 2 + 1] = s1 + __ldg(&bout[1]);
    }
}

// ---------------------------------------------------------------------------
extern "C" void kernel_launch(void* const* d_in, const int* in_sizes, int n_in,
                              void* d_out, int out_size) {
    const float* x    = (const float*)d_in[0];
    const void*  ei   = d_in[1];
    const float* Wl0  = (const float*)d_in[2];
    const float* Wr0  = (const float*)d_in[3];
    const float* b0   = (const float*)d_in[4];
    const float* gm0  = (const float*)d_in[5];
    const float* be0  = (const float*)d_in[6];
    const float* Wl1  = (const float*)d_in[7];
    const float* Wr1  = (const float*)d_in[8];
    const float* b1   = (const float*)d_in[9];
    const float* gm1  = (const float*)d_in[10];
    const float* be1  = (const float*)d_in[11];
    const float* Wout = (const float*)d_in[12];
    const float* bout = (const float*)d_in[13];
    float* out = (float*)d_out;

    int E = in_sizes[1] / 2;  if (E > MAXE) E = MAXE;
    int n = out_size / 2;     if (n > MAXN) n = MAXN;

    cudaFuncSetAttribute(k_gemm_mma,
        cudaFuncAttributeMaxDynamicSharedMemorySize, SM_TOTAL);

    int eb  = (E + 255) / 256;
    int nb  = (n + 255) / 256;
    int ab  = (n * 32 + 255) / 256;              // float4-group per thread
    int ab2 = (n * 16 + 255) / 256;              // half-warp per node
    int gb  = (n + 127) / 128;
    int sbk = (n + 2047) / 2048;                 // scan chunks
    int pb  = (E + n * 32 + 65536 + 255) / 256;  // merged prep

    // --- CSR build + prep (5 launches) ---
    k_init   <<<nb, 256>>>(ei, E, n);
    k_edges  <<<eb, 256>>>(ei, E);
    k_scan1  <<<sbk, 256>>>(n);
    k_scan3  <<<nb, 256>>>(n);
    k_prep   <<<pb, 256>>>(x, Wl0, Wr0, Wl1, Wr1, E, n);

    // --- layer 0 ---
    k_aggregate<<<ab2, 256>>>(0, n);
    k_gemm_mma <<<gb, 256, SM_TOTAL>>>(0, 1, x, b0, nullptr, nullptr, n);
    k_apply_h  <<<ab, 256>>>(gm0, be0, n);

    // --- layer 1 ---
    k_aggregate<<<ab2, 256>>>(1, n);
    k_gemm_mma <<<gb, 256, SM_TOTAL>>>(1, 0, nullptr, b1, gm0, be0, n);

    // --- fused BN+ReLU+Linear[128->2] -> d_out ---
    k_apply_out<<<ab, 256>>>(Wout, bout, gm1, be1, out, n);
}

// round 12
// speedup vs baseline: 1.1393x; 1.0538x over previous
#include <cuda_runtime.h>
#include <cuda_bf16.h>
#include <cuda_fp16.h>
#include <cstdint>

// ---------------------------------------------------------------------------
// GraphSAGE persistent mega-kernel: the whole 2-layer pipeline in ONE launch.
// 148 blocks x 1024 threads, software grid barriers between phases:
//  P0 init -> P1 edge hist -> P2 scan1 | x->fp16 + W prep -> P3 scan fixup
//  -> P4 fill -> P5 agg L0 -> P6 gemm L0 -> P7 bn+relu->fp16
//  -> P8 agg L1 -> P9 gemm L1 -> P10 bn+relu+linear[128,2] -> out
// GEMM: mma.sync m16n8k16 bf16 split x3 (hi*hi+hi*lo+lo*hi), 128x128 tiles,
// 32 warps/tile (warp = 32 rows x 16 cols), BN stats fused in epilogue.
// Cross-phase RAW made safe with __ldcg where an SM may hold a stale L1 line.
// ---------------------------------------------------------------------------

#define MAXN 50000
#define MAXE 1048576
#define NB 148
#define NT 1024

__device__ float g_hpre[MAXN * 128];
__device__ float g_agg [MAXN * 128];
__device__ __half g_xhalf[MAXN * 128];
__device__ __half g_hhalf[MAXN * 128];
__device__ __nv_bfloat16 g_wth [2][128 * 256];
__device__ __nv_bfloat16 g_wtl [2][128 * 256];
__device__ int   g_deg   [MAXN];
__device__ int   g_rowptr[MAXN + 1];
__device__ int   g_cursor[MAXN];
__device__ int   g_src   [MAXE];
__device__ int   g_dst   [MAXE];
__device__ int   g_ssort [MAXE];
__device__ int   g_bsum  [32];
__device__ float g_stats0[256];
__device__ float g_stats1[256];
__device__ int   g_is64;
__device__ int   g_barc = 0;
__device__ volatile int g_barp = 0;

// ---------------- helpers ----------------
__device__ __forceinline__ uint32_t s2u(const void* p) {
    uint32_t a;
    asm("{ .reg .u64 t; cvta.to.shared.u64 t, %1; cvt.u32.u64 %0, t; }"
        : "=r"(a) : "l"(p));
    return a;
}
__device__ __forceinline__ void ldm4(uint32_t* r, uint32_t addr) {
    asm volatile("ldmatrix.sync.aligned.m8n8.x4.shared.b16 {%0,%1,%2,%3}, [%4];"
        : "=r"(r[0]), "=r"(r[1]), "=r"(r[2]), "=r"(r[3]) : "r"(addr));
}
__device__ __forceinline__ void mma16816(float* d, const uint32_t* a,
                                         uint32_t b0, uint32_t b1) {
    asm volatile(
        "mma.sync.aligned.m16n8k16.row.col.f32.bf16.bf16.f32 "
        "{%0,%1,%2,%3}, {%4,%5,%6,%7}, {%8,%9}, {%0,%1,%2,%3};"
        : "+f"(d[0]), "+f"(d[1]), "+f"(d[2]), "+f"(d[3])
        : "r"(a[0]), "r"(a[1]), "r"(a[2]), "r"(a[3]), "r"(b0), "r"(b1));
}
__device__ __forceinline__ uint32_t pkbf(float a, float b) {
    __nv_bfloat162 h = __halves2bfloat162(__float2bfloat16(a), __float2bfloat16(b));
    return *(uint32_t*)&h;
}

// grid-wide barrier (all NB blocks resident by construction)
__device__ __forceinline__ void gsync() {
    __syncthreads();
    if (threadIdx.x == 0) {
        __threadfence();
        int gen = g_barp;
        if (atomicAdd(&g_barc, 1) == (int)gridDim.x - 1) {
            g_barc = 0;
            __threadfence();
            g_barp = gen + 1;
        } else {
            while (g_barp == gen) __nanosleep(32);
            __threadfence();
        }
    }
    __syncthreads();
}

// BN finalize from raw stats into smem scale/shift (stats read via __ldcg)
__device__ __forceinline__ void finalize_smem(
        const float* __restrict__ stats, const float* __restrict__ gamma,
        const float* __restrict__ beta, int n, float* s_sc, float* s_sh) {
    int t = threadIdx.x;
    if (t < 128) {
        float invn = 1.0f / (float)n;
        float mu  = __ldcg(&stats[t]) * invn;
        float var = fmaxf(__ldcg(&stats[128 + t]) * invn - mu * mu, 0.f);
        float rs  = rsqrtf(var + 1e-5f);
        float sc  = __ldg(&gamma[t]) * rs;
        s_sc[t] = sc;
        s_sh[t] = __ldg(&beta[t]) - mu * sc;
    }
    __syncthreads();
}

// smem layout for GEMM (dynamic)
#define SM_A  0            // A: 2 halves x 4 k-sections x [128r][64c bf16] = 131072
#define SM_W  131072       // W chunk: 2 halves x 2 k-sections x [128n][64k] = 65536
#define SM_TOTAL 196608

// ---------------- aggregation phase: half-warp per node ----------------
__device__ __forceinline__ void agg_phase(int layer, int n) {
    int hw     = (blockIdx.x * NT + threadIdx.x) >> 4;
    int lane   = threadIdx.x & 15;
    int stride = (gridDim.x * NT) >> 4;
    const uint4* in4 = (const uint4*)(layer ? g_hhalf : g_xhalf);
    for (int node = hw; node < n; node += stride) {
        int e0 = __ldcg(&g_rowptr[node]), e1 = __ldcg(&g_rowptr[node + 1]);
        float acc[8] = {0.f, 0.f, 0.f, 0.f, 0.f, 0.f, 0.f, 0.f};
        #pragma unroll 4
        for (int e = e0; e < e1; e++) {
            int s = __ldg(&g_ssort[e]);
            uint4 p = __ldg(&in4[s * 16 + lane]);
            const __half2* h = (const __half2*)&p;
            #pragma unroll
            for (int q = 0; q < 4; q++) {
                float2 f = __half22float2(h[q]);
                acc[2 * q]     += f.x;
                acc[2 * q + 1] += f.y;
            }
        }
        float inv = 1.0f / fmaxf((float)(e1 - e0), 1.0f);
        float4* outp = (float4*)(g_agg + (size_t)node * 128 + lane * 8);
        outp[0] = make_float4(acc[0]*inv, acc[1]*inv, acc[2]*inv, acc[3]*inv);
        outp[1] = make_float4(acc[4]*inv, acc[5]*inv, acc[6]*inv, acc[7]*inv);
    }
}

// ---------------- GEMM phase: 128x128 tiles, 32 warps/tile ----------------
__device__ __forceinline__ void gemm_phase(
    int layer, int use_x, const float* __restrict__ xext,
    const float* __restrict__ bias, const float* s_sc, const float* s_sh,
    char* smem, int n)
{
    uint32_t sb = s2u(smem);
    int tid = threadIdx.x, wid = tid >> 5, lane = tid & 31;
    float* stats_out = layer ? g_stats1 : g_stats0;
    const __nv_bfloat16* wth = g_wth[layer];
    const __nv_bfloat16* wtl = g_wtl[layer];
    int wm = wid >> 3, wn = wid & 7;
    int m0 = wm * 32, n0 = wn * 16;
    int lx = lane & 7;
    int aRow = lane & 15, aKoff = lane >> 4;
    int wRow = (lane & 7) + ((lane >> 4) << 3), wKoff = (lane >> 3) & 1;
    int ntiles = (n + 127) >> 7;
    const float4* agg4 = (const float4*)g_agg;

    for (int t = blockIdx.x; t < ntiles; t += gridDim.x) {
        int row0 = t << 7;
        __syncthreads();   // prior tile's mainloop done before A overwrite
        // ---- A tile: fp32 load, inline bf16 hi/lo split, SW128 store ----
        for (int i = tid; i < 8192; i += NT) {
            int r = i >> 6, c4 = i & 63, c0 = c4 * 4;
            int row = row0 + r;
            float4 v = make_float4(0.f, 0.f, 0.f, 0.f);
            if (row < n) {
                if (c0 < 128) {
                    v = __ldcg(&agg4[row * 32 + c4]);
                } else if (use_x) {
                    v = __ldg(&((const float4*)xext)[row * 32 + (c4 - 32)]);
                } else {
                    int cc = c0 - 128;
                    v = *(const float4*)(g_hpre + (size_t)row * 128 + cc);
                    float4 sc = *(const float4*)(s_sc + cc);
                    float4 sh = *(const float4*)(s_sh + cc);
                    v.x = fmaxf(v.x * sc.x + sh.x, 0.f);
                    v.y = fmaxf(v.y * sc.y + sh.y, 0.f);
                    v.z = fmaxf(v.z * sc.z + sh.z, 0.f);
                    v.w = fmaxf(v.w * sc.w + sh.w, 0.f);
                }
            }
            float hx = __bfloat162float(__float2bfloat16(v.x));
            float hy = __bfloat162float(__float2bfloat16(v.y));
            float hz = __bfloat162float(__float2bfloat16(v.z));
            float hw = __bfloat162float(__float2bfloat16(v.w));
            uint2 hi = make_uint2(pkbf(v.x, v.y), pkbf(v.z, v.w));
            uint2 lo = make_uint2(pkbf(v.x - hx, v.y - hy), pkbf(v.z - hz, v.w - hw));
            int s   = c0 >> 6;
            int cc  = c0 & 63;
            int gin = cc >> 3;
            int hg  = (cc >> 2) & 1;
            char* dst = smem + SM_A + s * 16384 + r * 128 +
                        ((gin ^ (r & 7)) * 16) + hg * 8;
            *(uint2*)dst = hi;
            *(uint2*)(dst + 65536) = lo;
        }

        float acc[2][2][4];
        #pragma unroll
        for (int mf = 0; mf < 2; mf++)
            #pragma unroll
            for (int nf = 0; nf < 2; nf++)
                #pragma unroll
                for (int q = 0; q < 4; q++) acc[mf][nf][q] = 0.f;

        #pragma unroll 1
        for (int kc = 0; kc < 2; kc++) {
            __syncthreads();
            // ---- W chunk (hi + lo) ----
            for (int i = tid; i < 4096; i += NT) {
                int half = i >> 11;
                int j = i & 2047;
                int r = j >> 4;
                int kin = (j & 15) * 8;
                int s2 = kin >> 6;
                int gin = (kin >> 3) & 7;
                const __nv_bfloat16* base = half ? wtl : wth;
                uint4 v = __ldg((const uint4*)(base + (size_t)r * 256 + kc * 128 + kin));
                *(uint4*)(smem + SM_W + half * 32768 + s2 * 16384 + r * 128 +
                          ((gin ^ (r & 7)) * 16)) = v;
            }
            __syncthreads();

            #pragma unroll 1
            for (int ksl = 0; ksl < 8; ksl++) {
                int ks  = kc * 8 + ksl;
                int sA  = ks >> 2;
                int kgA = (ks & 3) * 2 + aKoff;
                int s2  = ksl >> 2;
                int kgW = (ksl & 3) * 2 + wKoff;
                uint32_t wfh[4], wfl[4];
                {
                    int r = n0 + wRow;
                    uint32_t a = sb + SM_W + s2 * 16384 + r * 128 + ((kgW ^ lx) * 16);
                    ldm4(wfh, a);
                    ldm4(wfl, a + 32768);
                }
                #pragma unroll
                for (int ah = 0; ah < 2; ah++) {
                    uint32_t af[2][4];
                    #pragma unroll
                    for (int mf = 0; mf < 2; mf++) {
                        int r = m0 + mf * 16 + aRow;
                        ldm4(af[mf], sb + SM_A + ah * 65536 + sA * 16384 +
                                     r * 128 + ((kgA ^ lx) * 16));
                    }
                    #pragma unroll
                    for (int mf = 0; mf < 2; mf++) {
                        mma16816(acc[mf][0], af[mf], wfh[0], wfh[1]);
                        mma16816(acc[mf][1], af[mf], wfh[2], wfh[3]);
                    }
                    if (ah == 0) {
                        #pragma unroll
                        for (int mf = 0; mf < 2; mf++) {
                            mma16816(acc[mf][0], af[mf], wfl[0], wfl[1]);
                            mma16816(acc[mf][1], af[mf], wfl[2], wfl[3]);
                        }
                    }
                }
            }
        }

        // ---- epilogue: bias, store fp32, fused BN stats ----
        #pragma unroll
        for (int nf = 0; nf < 2; nf++) {
            int col = n0 + nf * 8 + (lane & 3) * 2;
            float bx = __ldg(&bias[col]), by = __ldg(&bias[col + 1]);
            float s0 = 0.f, q0 = 0.f, s1 = 0.f, q1 = 0.f;
            #pragma unroll
            for (int mf = 0; mf < 2; mf++) {
                int row = row0 + m0 + mf * 16 + (lane >> 2);
                if (row < n) {
                    float a = acc[mf][nf][0] + bx, b = acc[mf][nf][1] + by;
                    *(float2*)(g_hpre + (size_t)row * 128 + col) = make_float2(a, b);
                    s0 += a; q0 += a * a; s1 += b; q1 += b * b;
                }
                if (row + 8 < n) {
                    float a = acc[mf][nf][2] + bx, b = acc[mf][nf][3] + by;
                    *(float2*)(g_hpre + (size_t)(row + 8) * 128 + col) = make_float2(a, b);
                    s0 += a; q0 += a * a; s1 += b; q1 += b * b;
                }
            }
            #pragma unroll
            for (int off = 4; off < 32; off <<= 1) {
                s0 += __shfl_xor_sync(0xffffffffu, s0, off);
                q0 += __shfl_xor_sync(0xffffffffu, q0, off);
                s1 += __shfl_xor_sync(0xffffffffu, s1, off);
                q1 += __shfl_xor_sync(0xffffffffu, q1, off);
            }
            if (lane < 4) {
                int c = n0 + nf * 8 + lane * 2;
                atomicAdd(&stats_out[c],       s0);
                atomicAdd(&stats_out[128 + c], q0);
                atomicAdd(&stats_out[c + 1],       s1);
                atomicAdd(&stats_out[128 + c + 1], q1);
            }
        }
    }
}

// ---------------- the mega kernel ----------------
__global__ void __launch_bounds__(NT, 1)
k_mega(const float* __restrict__ x, const void* __restrict__ ei,
       const float* __restrict__ Wl0, const float* __restrict__ Wr0,
       const float* __restrict__ b0,
       const float* __restrict__ gm0, const float* __restrict__ be0,
       const float* __restrict__ Wl1, const float* __restrict__ Wr1,
       const float* __restrict__ b1,
       const float* __restrict__ gm1, const float* __restrict__ be1,
       const float* __restrict__ Wout, const float* __restrict__ bout,
       float* __restrict__ out, int E, int n)
{
    extern __shared__ char smem[];
    __shared__ __align__(16) float s_sc[128];
    __shared__ __align__(16) float s_sh[128];
    __shared__ int s_ws[32];
    int tid  = threadIdx.x, bid = blockIdx.x;
    int gtid = bid * NT + tid;
    int gsz  = gridDim.x * NT;
    int lane = tid & 31, wid = tid >> 5;

    // ---- P0: init ----
    if (gtid == 0) {
        const int* p = (const int*)ei;
        int m = E < 64 ? E : 64, is64 = 1;
        for (int j = 0; j < m; j++)
            if (p[2 * j + 1] != 0) { is64 = 0; break; }
        g_is64 = is64;
    }
    for (int i = gtid; i < n; i += gsz) { g_deg[i] = 0; g_cursor[i] = 0; }
    if (gtid < 256) { g_stats0[gtid] = 0.f; g_stats1[gtid] = 0.f; }
    gsync();

    // ---- P1: decode edges + degree histogram ----
    {
        int is64 = g_is64;
        for (int i = gtid; i < E; i += gsz) {
            int s, d;
            if (is64) {
                const long long* q = (const long long*)ei;
                s = (int)q[i]; d = (int)q[E + i];
            } else {
                const int* q = (const int*)ei;
                s = q[i]; d = q[E + i];
            }
            g_src[i] = s; g_dst[i] = d;
            atomicAdd(&g_deg[d], 1);
        }
    }
    gsync();

    // ---- P2: per-chunk scan (blocks < sbk) | x->fp16 + W prep (others) ----
    int sbk = (n + 2047) >> 11;
    if (bid < sbk) {
        int i0 = bid * 2048 + tid * 2;
        int v0 = (i0     < n) ? __ldcg(&g_deg[i0])     : 0;
        int v1 = (i0 + 1 < n) ? __ldcg(&g_deg[i0 + 1]) : 0;
        int tot = v0 + v1;
        int xsc = tot;
        #pragma unroll
        for (int off = 1; off < 32; off <<= 1) {
            int t = __shfl_up_sync(0xffffffffu, xsc, off);
            if (lane >= off) xsc += t;
        }
        if (lane == 31) s_ws[wid] = xsc;
        __syncthreads();
        if (wid == 0) {
            int w = s_ws[lane];
            #pragma unroll
            for (int off = 1; off < 32; off <<= 1) {
                int t = __shfl_up_sync(0xffffffffu, w, off);
                if (lane >= off) w += t;
            }
            s_ws[lane] = w;
        }
        __syncthreads();
        int wpref = wid ? s_ws[wid - 1] : 0;
        int incl  = wpref + xsc;
        if (i0     < n) g_rowptr[i0 + 1] = incl - v1;
        if (i0 + 1 < n) g_rowptr[i0 + 2] = incl;
        if (tid == 0) g_bsum[bid] = s_ws[31];
    } else {
        int rb = bid - sbk, nrb = gridDim.x - sbk;
        for (int i = rb * NT + tid; i < n * 32; i += nrb * NT) {
            float4 v = __ldg(&((const float4*)x)[i]);
            __half2 a = __floats2half2_rn(v.x, v.y);
            __half2 b = __floats2half2_rn(v.z, v.w);
            ((uint2*)g_xhalf)[i] = make_uint2(*(uint32_t*)&a, *(uint32_t*)&b);
        }
        for (int i = rb * NT + tid; i < 65536; i += nrb * NT) {
            int layer = i >> 15;
            int t2 = i & 32767;
            int nn = t2 >> 8, k = t2 & 255;
            const float* Wl = layer ? Wl1 : Wl0;
            const float* Wr = layer ? Wr1 : Wr0;
            float v = (k < 128) ? __ldg(&Wl[k * 128 + nn])
                                : __ldg(&Wr[(k - 128) * 128 + nn]);
            __nv_bfloat16 h = __float2bfloat16(v);
            g_wth[layer][t2] = h;
            g_wtl[layer][t2] = __float2bfloat16(v - __bfloat162float(h));
        }
    }
    gsync();

    // ---- P3: scan fixup (inline small exclusive scan of block sums) ----
    for (int i = gtid; i < n; i += gsz) {
        int c = i >> 11, off = 0;
        for (int j = 0; j < c; j++) off += __ldcg(&g_bsum[j]);
        g_rowptr[i + 1] += off;
    }
    if (gtid == 0) g_rowptr[0] = 0;
    gsync();

    // ---- P4: fill sorted edge list ----
    for (int i = gtid; i < E; i += gsz) {
        int d = g_dst[i];
        int p = __ldcg(&g_rowptr[d]) + atomicAdd(&g_cursor[d], 1);
        g_ssort[p] = g_src[i];
    }
    gsync();

    // ---- P5: aggregate L0 ----
    agg_phase(0, n);
    gsync();

    // ---- P6: GEMM L0 (+stats0) ----
    gemm_phase(0, 1, x, b0, s_sc, s_sh, smem, n);
    gsync();

    // ---- P7: BN+ReLU -> fp16 ----
    finalize_smem(g_stats0, gm0, be0, n, s_sc, s_sh);
    for (int i = gtid; i < n * 32; i += gsz) {
        int cg = i & 31;
        float4 v  = ((const float4*)g_hpre)[i];
        float4 sc = ((const float4*)s_sc)[cg];
        float4 sh = ((const float4*)s_sh)[cg];
        v.x = fmaxf(v.x * sc.x + sh.x, 0.f);
        v.y = fmaxf(v.y * sc.y + sh.y, 0.f);
        v.z = fmaxf(v.z * sc.z + sh.z, 0.f);
        v.w = fmaxf(v.w * sc.w + sh.w, 0.f);
        __half2 a = __floats2half2_rn(v.x, v.y);
        __half2 b = __floats2half2_rn(v.z, v.w);
        ((uint2*)g_hhalf)[i] = make_uint2(*(uint32_t*)&a, *(uint32_t*)&b);
    }
    gsync();

    // ---- P8: aggregate L1 ----
    agg_phase(1, n);
    gsync();

    // ---- P9: GEMM L1 (self path uses s_sc/s_sh kept from P7) ----
    gemm_phase(1, 0, nullptr, b1, s_sc, s_sh, smem, n);
    gsync();

    // ---- P10: BN+ReLU + [128,2] linear -> out ----
    finalize_smem(g_stats1, gm1, be1, n, s_sc, s_sh);
    for (int node = gtid >> 5; node < n; node += gsz >> 5) {
        float4 v  = __ldcg(&((const float4*)g_hpre)[node * 32 + lane]);
        float4 sc = ((const float4*)s_sc)[lane];
        float4 sh = ((const float4*)s_sh)[lane];
        v.x = fmaxf(v.x * sc.x + sh.x, 0.f);
        v.y = fmaxf(v.y * sc.y + sh.y, 0.f);
        v.z = fmaxf(v.z * sc.z + sh.z, 0.f);
        v.w = fmaxf(v.w * sc.w + sh.w, 0.f);
        const float4* W4 = (const float4*)Wout;
        float4 wa = __ldg(&W4[lane * 2]);
        float4 wb = __ldg(&W4[lane * 2 + 1]);
        float s0 = v.x * wa.x + v.y * wa.z + v.z * wb.x + v.w * wb.z;
        float s1 = v.x * wa.y + v.y * wa.w + v.z * wb.y + v.w * wb.w;
        #pragma unroll
        for (int off = 16; off; off >>= 1) {
            s0 += __shfl_xor_sync(0xffffffffu, s0, off);
            s1 += __shfl_xor_sync(0xffffffffu, s1, off);
        }
        if (lane == 0) {
            out[node * 2 + 0] = s0 + __ldg(&bout[0]);
            out[node * 2 + 1] = s1 + __ldg(&bout[1]);
        }
    }
}

// ---------------------------------------------------------------------------
extern "C" void kernel_launch(void* const* d_in, const int* in_sizes, int n_in,
                              void* d_out, int out_size) {
    const float* x    = (const float*)d_in[0];
    const void*  ei   = d_in[1];
    const float* Wl0  = (const float*)d_in[2];
    const float* Wr0  = (const float*)d_in[3];
    const float* b0   = (const float*)d_in[4];
    const float* gm0  = (const float*)d_in[5];
    const float* be0  = (const float*)d_in[6];
    const float* Wl1  = (const float*)d_in[7];
    const float* Wr1  = (const float*)d_in[8];
    const float* b1   = (const float*)d_in[9];
    const float* gm1  = (const float*)d_in[10];
    const float* be1  = (const float*)d_in[11];
    const float* Wout = (const float*)d_in[12];
    const float* bout = (const float*)d_in[13];
    float* out = (float*)d_out;

    int E = in_sizes[1] / 2;  if (E > MAXE) E = MAXE;
    int n = out_size / 2;     if (n > MAXN) n = MAXN;

    cudaFuncSetAttribute(k_mega,
        cudaFuncAttributeMaxDynamicSharedMemorySize, SM_TOTAL);

    k_mega<<<NB, NT, SM_TOTAL>>>(x, ei, Wl0, Wr0, b0, gm0, be0,
                                 Wl1, Wr1, b1, gm1, be1, Wout, bout,
                                 out, E, n);
}

// round 13
// speedup vs baseline: 1.2310x; 1.0804x over previous
#include <cuda_runtime.h>
#include <cuda_bf16.h>
#include <cuda_fp16.h>
#include <cstdint>

// ---------------------------------------------------------------------------
// GraphSAGE persistent mega-kernel, aggregation fused into GEMM tiles.
// 148 blocks x 1024 threads, software grid barriers between phases:
//  P0 init -> P1 edge hist -> P2 scan | x->fp16 + W prep -> P3 scan fixup
//  -> P4 fill -> P5 fused agg+gemm L0 -> P6 bn+relu->fp16
//  -> P7 fused agg+gemm L1 -> P8 bn+relu+linear[128,2] -> out
// Each 128x128 GEMM tile gathers its own 128 nodes (half-warp x 2 rows)
// directly into the SW128 bf16 hi/lo A-tile smem — no g_agg round-trip.
// GEMM: mma.sync m16n8k16 bf16 split x3; BN stats fused in epilogue.
// ---------------------------------------------------------------------------

#define MAXN 50000
#define MAXE 1048576
#define NB 148
#define NT 1024

__device__ float g_hpre[MAXN * 128];
__device__ __half g_xhalf[MAXN * 128];
__device__ __half g_hhalf[MAXN * 128];
__device__ __nv_bfloat16 g_wth [2][128 * 256];
__device__ __nv_bfloat16 g_wtl [2][128 * 256];
__device__ int   g_deg   [MAXN];
__device__ int   g_rowptr[MAXN + 1];
__device__ int   g_cursor[MAXN];
__device__ int   g_src   [MAXE];
__device__ int   g_dst   [MAXE];
__device__ int   g_ssort [MAXE];
__device__ int   g_bsum  [32];
__device__ float g_stats0[256];
__device__ float g_stats1[256];
__device__ int   g_is64;
__device__ int   g_barc = 0;
__device__ volatile int g_barp = 0;

// ---------------- helpers ----------------
__device__ __forceinline__ uint32_t s2u(const void* p) {
    uint32_t a;
    asm("{ .reg .u64 t; cvta.to.shared.u64 t, %1; cvt.u32.u64 %0, t; }"
        : "=r"(a) : "l"(p));
    return a;
}
__device__ __forceinline__ void ldm4(uint32_t* r, uint32_t addr) {
    asm volatile("ldmatrix.sync.aligned.m8n8.x4.shared.b16 {%0,%1,%2,%3}, [%4];"
        : "=r"(r[0]), "=r"(r[1]), "=r"(r[2]), "=r"(r[3]) : "r"(addr));
}
__device__ __forceinline__ void mma16816(float* d, const uint32_t* a,
                                         uint32_t b0, uint32_t b1) {
    asm volatile(
        "mma.sync.aligned.m16n8k16.row.col.f32.bf16.bf16.f32 "
        "{%0,%1,%2,%3}, {%4,%5,%6,%7}, {%8,%9}, {%0,%1,%2,%3};"
        : "+f"(d[0]), "+f"(d[1]), "+f"(d[2]), "+f"(d[3])
        : "r"(a[0]), "r"(a[1]), "r"(a[2]), "r"(a[3]), "r"(b0), "r"(b1));
}
__device__ __forceinline__ uint32_t pkbf(float a, float b) {
    __nv_bfloat162 h = __halves2bfloat162(__float2bfloat16(a), __float2bfloat16(b));
    return *(uint32_t*)&h;
}

// grid-wide barrier (all NB blocks resident by construction)
__device__ __forceinline__ void gsync() {
    __syncthreads();
    if (threadIdx.x == 0) {
        __threadfence();
        int gen = g_barp;
        if (atomicAdd(&g_barc, 1) == (int)gridDim.x - 1) {
            g_barc = 0;
            __threadfence();
            g_barp = gen + 1;
        } else {
            while (g_barp == gen) __nanosleep(32);
            __threadfence();
        }
    }
    __syncthreads();
}

// BN finalize from raw stats into smem scale/shift
__device__ __forceinline__ void finalize_smem(
        const float* __restrict__ stats, const float* __restrict__ gamma,
        const float* __restrict__ beta, int n, float* s_sc, float* s_sh) {
    int t = threadIdx.x;
    if (t < 128) {
        float invn = 1.0f / (float)n;
        float mu  = __ldcg(&stats[t]) * invn;
        float var = fmaxf(__ldcg(&stats[128 + t]) * invn - mu * mu, 0.f);
        float rs  = rsqrtf(var + 1e-5f);
        float sc  = __ldg(&gamma[t]) * rs;
        s_sc[t] = sc;
        s_sh[t] = __ldg(&beta[t]) - mu * sc;
    }
    __syncthreads();
}

// smem layout for GEMM (dynamic)
#define SM_A  0            // A: 2 halves x 4 k-sections x [128r][64c bf16] = 131072
#define SM_W  131072       // W chunk: 2 halves x 2 k-sections x [128n][64k] = 65536
#define SM_TOTAL 196608

// ---------------- fused aggregate + GEMM phase ----------------
// Per 128x128 tile: 64 half-warps gather 2 node rows each (mean of fp16
// neighbor rows) and write bf16 hi/lo granules straight into the A tile;
// remaining A cols (self features) loaded fp32 and split; then mma mainloop.
__device__ __forceinline__ void agg_gemm_phase(
    int layer, int use_x, const float* __restrict__ xext,
    const float* __restrict__ bias, const float* s_sc, const float* s_sh,
    char* smem, int n)
{
    uint32_t sb = s2u(smem);
    int tid = threadIdx.x, wid = tid >> 5, lane = tid & 31;
    int hw = tid >> 4, lane16 = tid & 15;
    float* stats_out = layer ? g_stats1 : g_stats0;
    const __nv_bfloat16* wth = g_wth[layer];
    const __nv_bfloat16* wtl = g_wtl[layer];
    const uint4* gin4 = (const uint4*)(layer ? g_hhalf : g_xhalf);
    int wm = wid >> 3, wn = wid & 7;
    int m0 = wm * 32, n0 = wn * 16;
    int lx = lane & 7;
    int aRow = lane & 15, aKoff = lane >> 4;
    int wRow = (lane & 7) + ((lane >> 4) << 3), wKoff = (lane >> 3) & 1;
    int ntiles = (n + 127) >> 7;

    for (int t = blockIdx.x; t < ntiles; t += gridDim.x) {
        int row0 = t << 7;
        __syncthreads();   // prior tile's mainloop done before A overwrite

        // ---- fused aggregation: cols 0..127 of A (agg features) ----
        #pragma unroll 1
        for (int rr = 0; rr < 128; rr += 64) {
            int r = hw + rr;
            int node = row0 + r;
            float acc[8] = {0.f, 0.f, 0.f, 0.f, 0.f, 0.f, 0.f, 0.f};
            if (node < n) {
                int e0 = __ldcg(&g_rowptr[node]);
                int e1 = __ldcg(&g_rowptr[node + 1]);
                #pragma unroll 4
                for (int e = e0; e < e1; e++) {
                    int s = __ldg(&g_ssort[e]);
                    uint4 p = __ldg(&gin4[s * 16 + lane16]);
                    const __half2* h = (const __half2*)&p;
                    #pragma unroll
                    for (int q = 0; q < 4; q++) {
                        float2 f = __half22float2(h[q]);
                        acc[2 * q]     += f.x;
                        acc[2 * q + 1] += f.y;
                    }
                }
                float inv = 1.0f / fmaxf((float)(e1 - e0), 1.0f);
                #pragma unroll
                for (int q = 0; q < 8; q++) acc[q] *= inv;
            }
            uint4 hi = make_uint4(pkbf(acc[0], acc[1]), pkbf(acc[2], acc[3]),
                                  pkbf(acc[4], acc[5]), pkbf(acc[6], acc[7]));
            float rsd[8];
            #pragma unroll
            for (int q = 0; q < 8; q++)
                rsd[q] = acc[q] - __bfloat162float(__float2bfloat16(acc[q]));
            uint4 lo = make_uint4(pkbf(rsd[0], rsd[1]), pkbf(rsd[2], rsd[3]),
                                  pkbf(rsd[4], rsd[5]), pkbf(rsd[6], rsd[7]));
            int s   = lane16 >> 3;               // section (cols 0-63 / 64-127)
            int gin = lane16 & 7;                // 16B granule
            char* dst = smem + SM_A + s * 16384 + r * 128 + ((gin ^ (r & 7)) * 16);
            *(uint4*)dst = hi;
            *(uint4*)(dst + 65536) = lo;
        }

        // ---- self features: cols 128..255 of A ----
        for (int i = tid; i < 4096; i += NT) {
            int r = i >> 5, c4i = i & 31;
            int c0 = 128 + c4i * 4;
            int row = row0 + r;
            float4 v = make_float4(0.f, 0.f, 0.f, 0.f);
            if (row < n) {
                if (use_x) {
                    v = __ldg(&((const float4*)xext)[row * 32 + c4i]);
                } else {
                    int cc = c4i * 4;
                    v = *(const float4*)(g_hpre + (size_t)row * 128 + cc);
                    float4 sc = *(const float4*)(s_sc + cc);
                    float4 sh = *(const float4*)(s_sh + cc);
                    v.x = fmaxf(v.x * sc.x + sh.x, 0.f);
                    v.y = fmaxf(v.y * sc.y + sh.y, 0.f);
                    v.z = fmaxf(v.z * sc.z + sh.z, 0.f);
                    v.w = fmaxf(v.w * sc.w + sh.w, 0.f);
                }
            }
            float hx = __bfloat162float(__float2bfloat16(v.x));
            float hy = __bfloat162float(__float2bfloat16(v.y));
            float hz = __bfloat162float(__float2bfloat16(v.z));
            float hw2 = __bfloat162float(__float2bfloat16(v.w));
            uint2 hi = make_uint2(pkbf(v.x, v.y), pkbf(v.z, v.w));
            uint2 lo = make_uint2(pkbf(v.x - hx, v.y - hy), pkbf(v.z - hz, v.w - hw2));
            int s   = c0 >> 6;
            int cc  = c0 & 63;
            int gin = cc >> 3;
            int hg  = (cc >> 2) & 1;
            char* dst = smem + SM_A + s * 16384 + r * 128 +
                        ((gin ^ (r & 7)) * 16) + hg * 8;
            *(uint2*)dst = hi;
            *(uint2*)(dst + 65536) = lo;
        }

        float acc[2][2][4];
        #pragma unroll
        for (int mf = 0; mf < 2; mf++)
            #pragma unroll
            for (int nf = 0; nf < 2; nf++)
                #pragma unroll
                for (int q = 0; q < 4; q++) acc[mf][nf][q] = 0.f;

        #pragma unroll 1
        for (int kc = 0; kc < 2; kc++) {
            __syncthreads();
            // ---- W chunk (hi + lo) ----
            for (int i = tid; i < 4096; i += NT) {
                int half = i >> 11;
                int j = i & 2047;
                int r = j >> 4;
                int kin = (j & 15) * 8;
                int s2 = kin >> 6;
                int gin = (kin >> 3) & 7;
                const __nv_bfloat16* base = half ? wtl : wth;
                uint4 v = __ldg((const uint4*)(base + (size_t)r * 256 + kc * 128 + kin));
                *(uint4*)(smem + SM_W + half * 32768 + s2 * 16384 + r * 128 +
                          ((gin ^ (r & 7)) * 16)) = v;
            }
            __syncthreads();

            #pragma unroll 1
            for (int ksl = 0; ksl < 8; ksl++) {
                int ks  = kc * 8 + ksl;
                int sA  = ks >> 2;
                int kgA = (ks & 3) * 2 + aKoff;
                int s2  = ksl >> 2;
                int kgW = (ksl & 3) * 2 + wKoff;
                uint32_t wfh[4], wfl[4];
                {
                    int r = n0 + wRow;
                    uint32_t a = sb + SM_W + s2 * 16384 + r * 128 + ((kgW ^ lx) * 16);
                    ldm4(wfh, a);
                    ldm4(wfl, a + 32768);
                }
                #pragma unroll
                for (int ah = 0; ah < 2; ah++) {
                    uint32_t af[2][4];
                    #pragma unroll
                    for (int mf = 0; mf < 2; mf++) {
                        int r = m0 + mf * 16 + aRow;
                        ldm4(af[mf], sb + SM_A + ah * 65536 + sA * 16384 +
                                     r * 128 + ((kgA ^ lx) * 16));
                    }
                    #pragma unroll
                    for (int mf = 0; mf < 2; mf++) {
                        mma16816(acc[mf][0], af[mf], wfh[0], wfh[1]);
                        mma16816(acc[mf][1], af[mf], wfh[2], wfh[3]);
                    }
                    if (ah == 0) {
                        #pragma unroll
                        for (int mf = 0; mf < 2; mf++) {
                            mma16816(acc[mf][0], af[mf], wfl[0], wfl[1]);
                            mma16816(acc[mf][1], af[mf], wfl[2], wfl[3]);
                        }
                    }
                }
            }
        }

        // ---- epilogue: bias, store fp32, fused BN stats ----
        #pragma unroll
        for (int nf = 0; nf < 2; nf++) {
            int col = n0 + nf * 8 + (lane & 3) * 2;
            float bx = __ldg(&bias[col]), by = __ldg(&bias[col + 1]);
            float s0 = 0.f, q0 = 0.f, s1 = 0.f, q1 = 0.f;
            #pragma unroll
            for (int mf = 0; mf < 2; mf++) {
                int row = row0 + m0 + mf * 16 + (lane >> 2);
                if (row < n) {
                    float a = acc[mf][nf][0] + bx, b = acc[mf][nf][1] + by;
                    *(float2*)(g_hpre + (size_t)row * 128 + col) = make_float2(a, b);
                    s0 += a; q0 += a * a; s1 += b; q1 += b * b;
                }
                if (row + 8 < n) {
                    float a = acc[mf][nf][2] + bx, b = acc[mf][nf][3] + by;
                    *(float2*)(g_hpre + (size_t)(row + 8) * 128 + col) = make_float2(a, b);
                    s0 += a; q0 += a * a; s1 += b; q1 += b * b;
                }
            }
            #pragma unroll
            for (int off = 4; off < 32; off <<= 1) {
                s0 += __shfl_xor_sync(0xffffffffu, s0, off);
                q0 += __shfl_xor_sync(0xffffffffu, q0, off);
                s1 += __shfl_xor_sync(0xffffffffu, s1, off);
                q1 += __shfl_xor_sync(0xffffffffu, q1, off);
            }
            if (lane < 4) {
                int c = n0 + nf * 8 + lane * 2;
                atomicAdd(&stats_out[c],       s0);
                atomicAdd(&stats_out[128 + c], q0);
                atomicAdd(&stats_out[c + 1],       s1);
                atomicAdd(&stats_out[128 + c + 1], q1);
            }
        }
    }
}

// ---------------- the mega kernel ----------------
__global__ void __launch_bounds__(NT, 1)
k_mega(const float* __restrict__ x, const void* __restrict__ ei,
       const float* __restrict__ Wl0, const float* __restrict__ Wr0,
       const float* __restrict__ b0,
       const float* __restrict__ gm0, const float* __restrict__ be0,
       const float* __restrict__ Wl1, const float* __restrict__ Wr1,
       const float* __restrict__ b1,
       const float* __restrict__ gm1, const float* __restrict__ be1,
       const float* __restrict__ Wout, const float* __restrict__ bout,
       float* __restrict__ out, int E, int n)
{
    extern __shared__ char smem[];
    __shared__ __align__(16) float s_sc[128];
    __shared__ __align__(16) float s_sh[128];
    __shared__ int s_ws[32];
    int tid  = threadIdx.x, bid = blockIdx.x;
    int gtid = bid * NT + tid;
    int gsz  = gridDim.x * NT;
    int lane = tid & 31, wid = tid >> 5;

    // ---- P0: init ----
    if (gtid == 0) {
        const int* p = (const int*)ei;
        int m = E < 64 ? E : 64, is64 = 1;
        for (int j = 0; j < m; j++)
            if (p[2 * j + 1] != 0) { is64 = 0; break; }
        g_is64 = is64;
    }
    for (int i = gtid; i < n; i += gsz) { g_deg[i] = 0; g_cursor[i] = 0; }
    if (gtid < 256) { g_stats0[gtid] = 0.f; g_stats1[gtid] = 0.f; }
    gsync();

    // ---- P1: decode edges + degree histogram ----
    {
        int is64 = g_is64;
        for (int i = gtid; i < E; i += gsz) {
            int s, d;
            if (is64) {
                const long long* q = (const long long*)ei;
                s = (int)q[i]; d = (int)q[E + i];
            } else {
                const int* q = (const int*)ei;
                s = q[i]; d = q[E + i];
            }
            g_src[i] = s; g_dst[i] = d;
            atomicAdd(&g_deg[d], 1);
        }
    }
    gsync();

    // ---- P2: per-chunk scan (blocks < sbk) | x->fp16 + W prep (others) ----
    int sbk = (n + 2047) >> 11;
    if (bid < sbk) {
        int i0 = bid * 2048 + tid * 2;
        int v0 = (i0     < n) ? __ldcg(&g_deg[i0])     : 0;
        int v1 = (i0 + 1 < n) ? __ldcg(&g_deg[i0 + 1]) : 0;
        int tot = v0 + v1;
        int xsc = tot;
        #pragma unroll
        for (int off = 1; off < 32; off <<= 1) {
            int t = __shfl_up_sync(0xffffffffu, xsc, off);
            if (lane >= off) xsc += t;
        }
        if (lane == 31) s_ws[wid] = xsc;
        __syncthreads();
        if (wid == 0) {
            int w = s_ws[lane];
            #pragma unroll
            for (int off = 1; off < 32; off <<= 1) {
                int t = __shfl_up_sync(0xffffffffu, w, off);
                if (lane >= off) w += t;
            }
            s_ws[lane] = w;
        }
        __syncthreads();
        int wpref = wid ? s_ws[wid - 1] : 0;
        int incl  = wpref + xsc;
        if (i0     < n) g_rowptr[i0 + 1] = incl - v1;
        if (i0 + 1 < n) g_rowptr[i0 + 2] = incl;
        if (tid == 0) g_bsum[bid] = s_ws[31];
    } else {
        int rb = bid - sbk, nrb = gridDim.x - sbk;
        for (int i = rb * NT + tid; i < n * 32; i += nrb * NT) {
            float4 v = __ldg(&((const float4*)x)[i]);
            __half2 a = __floats2half2_rn(v.x, v.y);
            __half2 b = __floats2half2_rn(v.z, v.w);
            ((uint2*)g_xhalf)[i] = make_uint2(*(uint32_t*)&a, *(uint32_t*)&b);
        }
        for (int i = rb * NT + tid; i < 65536; i += nrb * NT) {
            int layer = i >> 15;
            int t2 = i & 32767;
            int nn = t2 >> 8, k = t2 & 255;
            const float* Wl = layer ? Wl1 : Wl0;
            const float* Wr = layer ? Wr1 : Wr0;
            float v = (k < 128) ? __ldg(&Wl[k * 128 + nn])
                                : __ldg(&Wr[(k - 128) * 128 + nn]);
            __nv_bfloat16 h = __float2bfloat16(v);
            g_wth[layer][t2] = h;
            g_wtl[layer][t2] = __float2bfloat16(v - __bfloat162float(h));
        }
    }
    gsync();

    // ---- P3: scan fixup ----
    for (int i = gtid; i < n; i += gsz) {
        int c = i >> 11, off = 0;
        for (int j = 0; j < c; j++) off += __ldcg(&g_bsum[j]);
        g_rowptr[i + 1] += off;
    }
    if (gtid == 0) g_rowptr[0] = 0;
    gsync();

    // ---- P4: fill sorted edge list ----
    for (int i = gtid; i < E; i += gsz) {
        int d = g_dst[i];
        int p = __ldcg(&g_rowptr[d]) + atomicAdd(&g_cursor[d], 1);
        g_ssort[p] = g_src[i];
    }
    gsync();

    // ---- P5: fused agg+GEMM L0 (+stats0) ----
    agg_gemm_phase(0, 1, x, b0, s_sc, s_sh, smem, n);
    gsync();

    // ---- P6: BN+ReLU -> fp16 ----
    finalize_smem(g_stats0, gm0, be0, n, s_sc, s_sh);
    for (int i = gtid; i < n * 32; i += gsz) {
        int cg = i & 31;
        float4 v  = ((const float4*)g_hpre)[i];
        float4 sc = ((const float4*)s_sc)[cg];
        float4 sh = ((const float4*)s_sh)[cg];
        v.x = fmaxf(v.x * sc.x + sh.x, 0.f);
        v.y = fmaxf(v.y * sc.y + sh.y, 0.f);
        v.z = fmaxf(v.z * sc.z + sh.z, 0.f);
        v.w = fmaxf(v.w * sc.w + sh.w, 0.f);
        __half2 a = __floats2half2_rn(v.x, v.y);
        __half2 b = __floats2half2_rn(v.z, v.w);
        ((uint2*)g_hhalf)[i] = make_uint2(*(uint32_t*)&a, *(uint32_t*)&b);
    }
    gsync();

    // ---- P7: fused agg+GEMM L1 (self path uses s_sc/s_sh from P6) ----
    agg_gemm_phase(1, 0, nullptr, b1, s_sc, s_sh, smem, n);
    gsync();

    // ---- P8: BN+ReLU + [128,2] linear -> out ----
    finalize_smem(g_stats1, gm1, be1, n, s_sc, s_sh);
    for (int node = gtid >> 5; node < n; node += gsz >> 5) {
        float4 v  = __ldcg(&((const float4*)g_hpre)[node * 32 + lane]);
        float4 sc = ((const float4*)s_sc)[lane];
        float4 sh = ((const float4*)s_sh)[lane];
        v.x = fmaxf(v.x * sc.x + sh.x, 0.f);
        v.y = fmaxf(v.y * sc.y + sh.y, 0.f);
        v.z = fmaxf(v.z * sc.z + sh.z, 0.f);
        v.w = fmaxf(v.w * sc.w + sh.w, 0.f);
        const float4* W4 = (const float4*)Wout;
        float4 wa = __ldg(&W4[lane * 2]);
        float4 wb = __ldg(&W4[lane * 2 + 1]);
        float s0 = v.x * wa.x + v.y * wa.z + v.z * wb.x + v.w * wb.z;
        float s1 = v.x * wa.y + v.y * wa.w + v.z * wb.y + v.w * wb.w;
        #pragma unroll
        for (int off = 16; off; off >>= 1) {
            s0 += __shfl_xor_sync(0xffffffffu, s0, off);
            s1 += __shfl_xor_sync(0xffffffffu, s1, off);
        }
        if (lane == 0) {
            out[node * 2 + 0] = s0 + __ldg(&bout[0]);
            out[node * 2 + 1] = s1 + __ldg(&bout[1]);
        }
    }
}

// ---------------------------------------------------------------------------
extern "C" void kernel_launch(void* const* d_in, const int* in_sizes, int n_in,
                              void* d_out, int out_size) {
    const float* x    = (const float*)d_in[0];
    const void*  ei   = d_in[1];
    const float* Wl0  = (const float*)d_in[2];
    const float* Wr0  = (const float*)d_in[3];
    const float* b0   = (const float*)d_in[4];
    const float* gm0  = (const float*)d_in[5];
    const float* be0  = (const float*)d_in[6];
    const float* Wl1  = (const float*)d_in[7];
    const float* Wr1  = (const float*)d_in[8];
    const float* b1   = (const float*)d_in[9];
    const float* gm1  = (const float*)d_in[10];
    const float* be1  = (const float*)d_in[11];
    const float* Wout = (const float*)d_in[12];
    const float* bout = (const float*)d_in[13];
    float* out = (float*)d_out;

    int E = in_sizes[1] / 2;  if (E > MAXE) E = MAXE;
    int n = out_size / 2;     if (n > MAXN) n = MAXN;

    cudaFuncSetAttribute(k_mega,
        cudaFuncAttributeMaxDynamicSharedMemorySize, SM_TOTAL);

    k_mega<<<NB, NT, SM_TOTAL>>>(x, ei, Wl0, Wr0, b0, gm0, be0,
                                 Wl1, Wr1, b1, gm1, be1, Wout, bout,
                                 out, E, n);
}